// round 4
// baseline (speedup 1.0000x reference)
#include <cuda_runtime.h>
#include <cuda_bf16.h>
#include <cstdint>
#include <cstddef>

// Problem constants
#define BATCH 8
#define NQ 1024
#define NKV 1024
#define DMODEL 512
#define NH 8
#define DH 64
#define BH (BATCH*NH)          // 64
#define SCALE 0.125f           // DH^-0.5

// Scratch (allocation-free rule: __device__ globals)
__device__ float g_Q[(size_t)BH*NQ*DH];     // [bh][q][d]
__device__ float g_K[(size_t)BH*NKV*DH];    // [bh][k][d]
__device__ float g_V[(size_t)BH*NKV*DH];    // [bh][k][d]
__device__ float g_ctx[(size_t)BATCH*NQ*DMODEL]; // [b][q][h*64+d]
__device__ float g_scores_fallback[(size_t)BH*NQ*NKV]; // only if out buffer lacks attn region

// ---------------------------------------------------------------------------
// SGEMM: C[M,N] = A[M,K] @ W[K,N] + bias[N]
// permute==1: store to out[((b*8+h)*1024+n)*64+d]  (projection -> [b,h,n,d])
// Tiles: 128x128x16, 256 threads, 8x8 per thread.
// ---------------------------------------------------------------------------
__global__ __launch_bounds__(256) void sgemm_kernel(
    const float* __restrict__ A, const float* __restrict__ W,
    const float* __restrict__ bias, float* __restrict__ C,
    int M, int N, int K, int permute)
{
    __shared__ float As[16][132];  // [k][m] transposed
    __shared__ float Bs[16][132];  // [k][n]

    const int tid = threadIdx.x;
    const int tx = tid & 15;
    const int ty = tid >> 4;
    const int row0 = blockIdx.y * 128;
    const int col0 = blockIdx.x * 128;

    float acc[8][8];
    #pragma unroll
    for (int i = 0; i < 8; i++)
        #pragma unroll
        for (int j = 0; j < 8; j++) acc[i][j] = 0.f;

    for (int k0 = 0; k0 < K; k0 += 16) {
        #pragma unroll
        for (int i = 0; i < 2; i++) {
            int s = tid + i * 256;
            int r = s >> 2;
            int c4 = (s & 3) * 4;
            float4 v = *(const float4*)&A[(size_t)(row0 + r) * K + k0 + c4];
            As[c4 + 0][r] = v.x; As[c4 + 1][r] = v.y;
            As[c4 + 2][r] = v.z; As[c4 + 3][r] = v.w;
        }
        #pragma unroll
        for (int i = 0; i < 2; i++) {
            int s = tid + i * 256;
            int r = s >> 5;
            int c4 = (s & 31) * 4;
            *(float4*)&Bs[r][c4] = *(const float4*)&W[(size_t)(k0 + r) * N + col0 + c4];
        }
        __syncthreads();

        #pragma unroll
        for (int kk = 0; kk < 16; kk++) {
            float a[8], b[8];
            *(float4*)&a[0] = *(const float4*)&As[kk][ty * 8];
            *(float4*)&a[4] = *(const float4*)&As[kk][ty * 8 + 4];
            *(float4*)&b[0] = *(const float4*)&Bs[kk][tx * 8];
            *(float4*)&b[4] = *(const float4*)&Bs[kk][tx * 8 + 4];
            #pragma unroll
            for (int i = 0; i < 8; i++)
                #pragma unroll
                for (int j = 0; j < 8; j++)
                    acc[i][j] += a[i] * b[j];
        }
        __syncthreads();
    }

    #pragma unroll
    for (int i = 0; i < 8; i++) {
        int gr = row0 + ty * 8 + i;
        #pragma unroll
        for (int j = 0; j < 8; j++) {
            int gc = col0 + tx * 8 + j;
            float v = acc[i][j] + bias[gc];
            if (permute) {
                int b = gr >> 10, n = gr & 1023;
                int h = gc >> 6,  d = gc & 63;
                C[(((size_t)(b * NH + h)) * NQ + n) * DH + d] = v;
            } else {
                C[(size_t)gr * N + gc] = v;
            }
        }
    }
}

// ---------------------------------------------------------------------------
// QK^T: S[bh][q][k] = sum_d Q[bh][q][d]*K[bh][k][d]
// Block: 64x64 tile, one bh. 256 threads, 4x4 per thread.
// ---------------------------------------------------------------------------
__global__ __launch_bounds__(256) void qk_kernel(
    const float* __restrict__ Q, const float* __restrict__ Km,
    float* __restrict__ S)
{
    const int bh = blockIdx.z;
    const int q0 = blockIdx.y * 64;
    const int k0 = blockIdx.x * 64;
    const float* Qb = Q + (size_t)bh * NQ * DH;
    const float* Kb = Km + (size_t)bh * NKV * DH;

    __shared__ float Qs[64][68];  // [d][q]
    __shared__ float Ks[64][68];  // [d][k]

    const int tid = threadIdx.x;
    #pragma unroll
    for (int i = 0; i < 4; i++) {
        int s = tid + i * 256;
        int r = s >> 4;
        int c4 = (s & 15) * 4;
        float4 v = *(const float4*)&Qb[(size_t)(q0 + r) * DH + c4];
        Qs[c4 + 0][r] = v.x; Qs[c4 + 1][r] = v.y;
        Qs[c4 + 2][r] = v.z; Qs[c4 + 3][r] = v.w;
        float4 w = *(const float4*)&Kb[(size_t)(k0 + r) * DH + c4];
        Ks[c4 + 0][r] = w.x; Ks[c4 + 1][r] = w.y;
        Ks[c4 + 2][r] = w.z; Ks[c4 + 3][r] = w.w;
    }
    __syncthreads();

    const int tx = tid & 15;
    const int ty = tid >> 4;
    float acc[4][4];
    #pragma unroll
    for (int i = 0; i < 4; i++)
        #pragma unroll
        for (int j = 0; j < 4; j++) acc[i][j] = 0.f;

    #pragma unroll
    for (int d = 0; d < 64; d++) {
        float a[4], b[4];
        *(float4*)a = *(const float4*)&Qs[d][ty * 4];
        *(float4*)b = *(const float4*)&Ks[d][tx * 4];
        #pragma unroll
        for (int i = 0; i < 4; i++)
            #pragma unroll
            for (int j = 0; j < 4; j++)
                acc[i][j] += a[i] * b[j];
    }

    #pragma unroll
    for (int i = 0; i < 4; i++) {
        size_t base = ((size_t)bh * NQ + (q0 + ty * 4 + i)) * NKV + k0 + tx * 4;
        #pragma unroll
        for (int j = 0; j < 4; j++)
            S[base + j] = acc[i][j];
    }
}

// ---------------------------------------------------------------------------
// RPE bias + scale + mask (in place on S):
//   S[bh][q][k] = mask[b][k] ? (S + sum_d Q[bh][q][d]*R[q][k][d]) * SCALE : -1e30
// One block per (q, k_tile of 64). GEMM M=64(bh) N=64(k) K=64(d).
// R is read exactly once from HBM; reused 64x (bh) via smem.
// ---------------------------------------------------------------------------
__global__ __launch_bounds__(256) void rpe_bias_kernel(
    const float* __restrict__ Q, const float* __restrict__ R,
    const int* __restrict__ mask, float* __restrict__ S)
{
    const int q  = blockIdx.y;
    const int k0 = blockIdx.x * 64;

    __shared__ float Aqs[64][68]; // [d][bh]
    __shared__ float Rs[64][68];  // [d][k]

    const int tid = threadIdx.x;
    #pragma unroll
    for (int i = 0; i < 4; i++) {
        int s = tid + i * 256;
        int r = s >> 4;            // bh row / k row
        int c4 = (s & 15) * 4;     // d
        float4 v = *(const float4*)&Q[(((size_t)r * NQ) + q) * DH + c4];
        Aqs[c4 + 0][r] = v.x; Aqs[c4 + 1][r] = v.y;
        Aqs[c4 + 2][r] = v.z; Aqs[c4 + 3][r] = v.w;
        float4 w = *(const float4*)&R[(((size_t)q * NKV) + k0 + r) * DH + c4];
        Rs[c4 + 0][r] = w.x; Rs[c4 + 1][r] = w.y;
        Rs[c4 + 2][r] = w.z; Rs[c4 + 3][r] = w.w;
    }
    __syncthreads();

    const int tx = tid & 15;
    const int ty = tid >> 4;
    float acc[4][4];
    #pragma unroll
    for (int i = 0; i < 4; i++)
        #pragma unroll
        for (int j = 0; j < 4; j++) acc[i][j] = 0.f;

    #pragma unroll
    for (int d = 0; d < 64; d++) {
        float a[4], b[4];
        *(float4*)a = *(const float4*)&Aqs[d][ty * 4];
        *(float4*)b = *(const float4*)&Rs[d][tx * 4];
        #pragma unroll
        for (int i = 0; i < 4; i++)
            #pragma unroll
            for (int j = 0; j < 4; j++)
                acc[i][j] += a[i] * b[j];
    }

    #pragma unroll
    for (int i = 0; i < 4; i++) {
        int bh = ty * 4 + i;
        int b = bh >> 3;
        size_t base = ((size_t)bh * NQ + q) * NKV + k0 + tx * 4;
        #pragma unroll
        for (int j = 0; j < 4; j++) {
            int k = k0 + tx * 4 + j;
            float v = (S[base + j] + acc[i][j]) * SCALE;
            S[base + j] = (mask[b * NKV + k] != 0) ? v : -1e30f;
        }
    }
}

// ---------------------------------------------------------------------------
// Row softmax in place: one block (256 thr) per (bh,q) row of 1024.
// ---------------------------------------------------------------------------
__global__ __launch_bounds__(256) void softmax_kernel(float* __restrict__ S)
{
    const size_t row = blockIdx.x;
    float* p = S + row * NKV;
    const int tid = threadIdx.x;
    const int lane = tid & 31;
    const int warp = tid >> 5;

    __shared__ float red[8];

    float4 v = *(const float4*)&p[tid * 4];
    float m = fmaxf(fmaxf(v.x, v.y), fmaxf(v.z, v.w));
    #pragma unroll
    for (int o = 16; o > 0; o >>= 1)
        m = fmaxf(m, __shfl_xor_sync(0xFFFFFFFFu, m, o));
    if (lane == 0) red[warp] = m;
    __syncthreads();
    float M = red[0];
    #pragma unroll
    for (int w = 1; w < 8; w++) M = fmaxf(M, red[w]);
    __syncthreads();

    float e0 = expf(v.x - M);
    float e1 = expf(v.y - M);
    float e2 = expf(v.z - M);
    float e3 = expf(v.w - M);
    float s = e0 + e1 + e2 + e3;
    #pragma unroll
    for (int o = 16; o > 0; o >>= 1)
        s += __shfl_xor_sync(0xFFFFFFFFu, s, o);
    if (lane == 0) red[warp] = s;
    __syncthreads();
    float Sum = 0.f;
    #pragma unroll
    for (int w = 0; w < 8; w++) Sum += red[w];

    float inv = 1.f / Sum;
    float4 o4 = make_float4(e0 * inv, e1 * inv, e2 * inv, e3 * inv);
    *(float4*)&p[tid * 4] = o4;
}

// ---------------------------------------------------------------------------
// PV: ctx[b][q][h*64+d] = sum_k P[bh][q][k] * V[bh][k][d]
// Block: (q_tile 64, bh). 64x64 output, BK=32, 256 threads, 4x4/thread.
// ---------------------------------------------------------------------------
__global__ __launch_bounds__(256) void pv_kernel(
    const float* __restrict__ P, const float* __restrict__ V,
    float* __restrict__ ctx)
{
    const int bh = blockIdx.y;
    const int q0 = blockIdx.x * 64;
    const float* Pb = P + (size_t)bh * NQ * NKV;
    const float* Vb = V + (size_t)bh * NKV * DH;

    __shared__ float Ps[32][68]; // [k][q]
    __shared__ float Vs[32][68]; // [k][d]

    const int tid = threadIdx.x;
    const int tx = tid & 15;
    const int ty = tid >> 4;

    float acc[4][4];
    #pragma unroll
    for (int i = 0; i < 4; i++)
        #pragma unroll
        for (int j = 0; j < 4; j++) acc[i][j] = 0.f;

    for (int k0 = 0; k0 < NKV; k0 += 32) {
        #pragma unroll
        for (int i = 0; i < 2; i++) {
            int s = tid + i * 256;
            int r = s >> 3;
            int c4 = (s & 7) * 4;
            float4 v = *(const float4*)&Pb[(size_t)(q0 + r) * NKV + k0 + c4];
            Ps[c4 + 0][r] = v.x; Ps[c4 + 1][r] = v.y;
            Ps[c4 + 2][r] = v.z; Ps[c4 + 3][r] = v.w;
        }
        #pragma unroll
        for (int i = 0; i < 2; i++) {
            int s = tid + i * 256;
            int r = s >> 4;
            int c4 = (s & 15) * 4;
            *(float4*)&Vs[r][c4] = *(const float4*)&Vb[(size_t)(k0 + r) * DH + c4];
        }
        __syncthreads();

        #pragma unroll
        for (int kk = 0; kk < 32; kk++) {
            float a[4], b[4];
            *(float4*)a = *(const float4*)&Ps[kk][ty * 4];
            *(float4*)b = *(const float4*)&Vs[kk][tx * 4];
            #pragma unroll
            for (int i = 0; i < 4; i++)
                #pragma unroll
                for (int j = 0; j < 4; j++)
                    acc[i][j] += a[i] * b[j];
        }
        __syncthreads();
    }

    const int b = bh >> 3, h = bh & 7;
    #pragma unroll
    for (int i = 0; i < 4; i++) {
        int q = q0 + ty * 4 + i;
        size_t base = ((size_t)(b * NQ + q)) * DMODEL + h * DH + tx * 4;
        #pragma unroll
        for (int j = 0; j < 4; j++)
            ctx[base + j] = acc[i][j];
    }
}

// ---------------------------------------------------------------------------
extern "C" void kernel_launch(void* const* d_in, const int* in_sizes, int n_in,
                              void* d_out, int out_size)
{
    const float* q    = (const float*)d_in[0];
    const float* kv   = (const float*)d_in[1];
    const int*   mask = (const int*)  d_in[2];
    const float* Wq   = (const float*)d_in[3];
    const float* bq   = (const float*)d_in[4];
    const float* Wk   = (const float*)d_in[5];
    const float* bk   = (const float*)d_in[6];
    const float* Wv   = (const float*)d_in[7];
    const float* bv   = (const float*)d_in[8];
    const float* Wo   = (const float*)d_in[9];
    const float* bo   = (const float*)d_in[10];
    const float* R    = (const float*)d_in[11];

    float* out = (float*)d_out;
    const size_t out_elems  = (size_t)BATCH * NQ * DMODEL;       // 4,194,304
    const size_t attn_elems = (size_t)BH * NQ * NKV;             // 67,108,864

    // Resolve scratch addresses once (host-side statics; not stream ops)
    static float *Qp = nullptr, *Kp = nullptr, *Vp = nullptr, *ctx = nullptr, *fb = nullptr;
    if (!Qp) {
        cudaGetSymbolAddress((void**)&Qp,  g_Q);
        cudaGetSymbolAddress((void**)&Kp,  g_K);
        cudaGetSymbolAddress((void**)&Vp,  g_V);
        cudaGetSymbolAddress((void**)&ctx, g_ctx);
        cudaGetSymbolAddress((void**)&fb,  g_scores_fallback);
    }

    // scores buffer: attn region of d_out if present, else device scratch
    float* scores = ((size_t)out_size >= out_elems + attn_elems) ? (out + out_elems) : fb;

    const int M = BATCH * NQ;   // 8192
    dim3 gemm_grid(DMODEL / 128, M / 128);  // (4, 64)

    // 1-3: projections with [b,h,n,d] permuted store
    sgemm_kernel<<<gemm_grid, 256>>>(q,  Wq, bq, Qp, M, DMODEL, DMODEL, 1);
    sgemm_kernel<<<gemm_grid, 256>>>(kv, Wk, bk, Kp, M, DMODEL, DMODEL, 1);
    sgemm_kernel<<<gemm_grid, 256>>>(kv, Wv, bv, Vp, M, DMODEL, DMODEL, 1);

    // 4: S1 = Q K^T per bh
    dim3 qk_grid(NKV / 64, NQ / 64, BH);    // (16,16,64)
    qk_kernel<<<qk_grid, 256>>>(Qp, Kp, scores);

    // 5: S = mask ? (S1 + Q·R) * scale : -1e30   (R read once, 64x bh reuse)
    dim3 rpe_grid(NKV / 64, NQ);            // (16,1024)
    rpe_bias_kernel<<<rpe_grid, 256>>>(Qp, R, mask, scores);

    // 6: softmax rows in place -> attn
    softmax_kernel<<<BH * NQ, 256>>>(scores);

    // 7: ctx = attn @ V, stored [b,q,h*64+d]
    dim3 pv_grid(NQ / 64, BH);              // (16,64)
    pv_kernel<<<pv_grid, 256>>>(scores, Vp, ctx);

    // 8: out = ctx @ Wo + bo
    sgemm_kernel<<<gemm_grid, 256>>>(ctx, Wo, bo, out, M, DMODEL, DMODEL, 0);
}

// round 5
// speedup vs baseline: 1.0970x; 1.0970x over previous
#include <cuda_runtime.h>
#include <cuda_bf16.h>
#include <cstdint>
#include <cstddef>

// Problem constants
#define BATCH 8
#define NQ 1024
#define NKV 1024
#define DMODEL 512
#define NH 8
#define DH 64
#define BH (BATCH*NH)          // 64
#define SCALE 0.125f           // DH^-0.5

// Scratch (allocation-free rule: __device__ globals)
__device__ float g_Q[(size_t)BH*NQ*DH];     // [bh][q][d]
__device__ float g_K[(size_t)BH*NKV*DH];    // [bh][k][d]
__device__ float g_V[(size_t)BH*NKV*DH];    // [bh][k][d]
__device__ float g_ctx[(size_t)BATCH*NQ*DMODEL]; // [b][q][h*64+d]
__device__ float g_scores_fallback[(size_t)BH*NQ*NKV]; // only if out buffer lacks attn region

// ---------------------------------------------------------------------------
// SGEMM: C[M,N] = A[M,K] @ W[K,N] + bias[N]
// permute==1: store to out[((b*8+h)*1024+n)*64+d]  (projection -> [b,h,n,d])
// Tiles: 128x128x16, 256 threads, 8x8 per thread.
// ---------------------------------------------------------------------------
__global__ __launch_bounds__(256) void sgemm_kernel(
    const float* __restrict__ A, const float* __restrict__ W,
    const float* __restrict__ bias, float* __restrict__ C,
    int M, int N, int K, int permute)
{
    __shared__ float As[16][132];  // [k][m] transposed
    __shared__ float Bs[16][132];  // [k][n]

    const int tid = threadIdx.x;
    const int tx = tid & 15;
    const int ty = tid >> 4;
    const int row0 = blockIdx.y * 128;
    const int col0 = blockIdx.x * 128;

    float acc[8][8];
    #pragma unroll
    for (int i = 0; i < 8; i++)
        #pragma unroll
        for (int j = 0; j < 8; j++) acc[i][j] = 0.f;

    for (int k0 = 0; k0 < K; k0 += 16) {
        #pragma unroll
        for (int i = 0; i < 2; i++) {
            int s = tid + i * 256;
            int r = s >> 2;
            int c4 = (s & 3) * 4;
            float4 v = *(const float4*)&A[(size_t)(row0 + r) * K + k0 + c4];
            As[c4 + 0][r] = v.x; As[c4 + 1][r] = v.y;
            As[c4 + 2][r] = v.z; As[c4 + 3][r] = v.w;
        }
        #pragma unroll
        for (int i = 0; i < 2; i++) {
            int s = tid + i * 256;
            int r = s >> 5;
            int c4 = (s & 31) * 4;
            *(float4*)&Bs[r][c4] = *(const float4*)&W[(size_t)(k0 + r) * N + col0 + c4];
        }
        __syncthreads();

        #pragma unroll 8
        for (int kk = 0; kk < 16; kk++) {
            float a[8], b[8];
            *(float4*)&a[0] = *(const float4*)&As[kk][ty * 8];
            *(float4*)&a[4] = *(const float4*)&As[kk][ty * 8 + 4];
            *(float4*)&b[0] = *(const float4*)&Bs[kk][tx * 8];
            *(float4*)&b[4] = *(const float4*)&Bs[kk][tx * 8 + 4];
            #pragma unroll
            for (int i = 0; i < 8; i++)
                #pragma unroll
                for (int j = 0; j < 8; j++)
                    acc[i][j] += a[i] * b[j];
        }
        __syncthreads();
    }

    #pragma unroll
    for (int i = 0; i < 8; i++) {
        int gr = row0 + ty * 8 + i;
        #pragma unroll
        for (int j = 0; j < 8; j++) {
            int gc = col0 + tx * 8 + j;
            float v = acc[i][j] + bias[gc];
            if (permute) {
                int b = gr >> 10, n = gr & 1023;
                int h = gc >> 6,  d = gc & 63;
                C[(((size_t)(b * NH + h)) * NQ + n) * DH + d] = v;
            } else {
                C[(size_t)gr * N + gc] = v;
            }
        }
    }
}

// ---------------------------------------------------------------------------
// QK^T: S[bh][q][k] = sum_d Q[bh][q][d]*K[bh][k][d]
// Block: 128x128 tile per bh, 256 threads, 8x8 per thread, d chunked by 32.
// 1 byte LDS per FMA -> not crossbar-limited.
// ---------------------------------------------------------------------------
__global__ __launch_bounds__(256) void qk_kernel(
    const float* __restrict__ Q, const float* __restrict__ Km,
    float* __restrict__ S)
{
    const int bh = blockIdx.z;
    const int q0 = blockIdx.y * 128;
    const int k0 = blockIdx.x * 128;
    const float* Qb = Q + (size_t)bh * NQ * DH;
    const float* Kb = Km + (size_t)bh * NKV * DH;

    __shared__ float Qs[32][132];  // [d][q]
    __shared__ float Ks[32][132];  // [d][k]

    const int tid = threadIdx.x;
    const int tx = tid & 15;
    const int ty = tid >> 4;

    float acc[8][8];
    #pragma unroll
    for (int i = 0; i < 8; i++)
        #pragma unroll
        for (int j = 0; j < 8; j++) acc[i][j] = 0.f;

    #pragma unroll 1
    for (int d0 = 0; d0 < DH; d0 += 32) {
        // 128 rows x 8 float4 = 1024 float4 per tile; 256 thr -> 4 each
        #pragma unroll
        for (int i = 0; i < 4; i++) {
            int s = tid + i * 256;
            int r = s >> 3;
            int c4 = (s & 7) * 4;
            float4 v = *(const float4*)&Qb[(size_t)(q0 + r) * DH + d0 + c4];
            Qs[c4 + 0][r] = v.x; Qs[c4 + 1][r] = v.y;
            Qs[c4 + 2][r] = v.z; Qs[c4 + 3][r] = v.w;
            float4 w = *(const float4*)&Kb[(size_t)(k0 + r) * DH + d0 + c4];
            Ks[c4 + 0][r] = w.x; Ks[c4 + 1][r] = w.y;
            Ks[c4 + 2][r] = w.z; Ks[c4 + 3][r] = w.w;
        }
        __syncthreads();

        #pragma unroll 8
        for (int dd = 0; dd < 32; dd++) {
            float a[8], b[8];
            *(float4*)&a[0] = *(const float4*)&Qs[dd][ty * 8];
            *(float4*)&a[4] = *(const float4*)&Qs[dd][ty * 8 + 4];
            *(float4*)&b[0] = *(const float4*)&Ks[dd][tx * 8];
            *(float4*)&b[4] = *(const float4*)&Ks[dd][tx * 8 + 4];
            #pragma unroll
            for (int i = 0; i < 8; i++)
                #pragma unroll
                for (int j = 0; j < 8; j++)
                    acc[i][j] += a[i] * b[j];
        }
        __syncthreads();
    }

    #pragma unroll
    for (int i = 0; i < 8; i++) {
        size_t base = ((size_t)bh * NQ + (q0 + ty * 8 + i)) * NKV + k0 + tx * 8;
        *(float4*)&S[base]     = *(float4*)&acc[i][0];
        *(float4*)&S[base + 4] = *(float4*)&acc[i][4];
    }
}

// ---------------------------------------------------------------------------
// RPE bias + scale + mask (in place on S):
//   S[bh][q][k] = mask[b][k] ? (S + sum_d Q[bh][q][d]*R[q][k][d]) * SCALE : -1e30
// Block per (q, k_tile of 128): GEMM M=64(bh) N=128(k) K=64(d), 128 thr, 8x8.
// R is read exactly once from HBM; reused 64x (bh) via smem.
// ---------------------------------------------------------------------------
__global__ __launch_bounds__(128) void rpe_bias_kernel(
    const float* __restrict__ Q, const float* __restrict__ R,
    const int* __restrict__ mask, float* __restrict__ S)
{
    const int q  = blockIdx.y;
    const int k0 = blockIdx.x * 128;

    __shared__ float Aqs[32][68];  // [d][bh]
    __shared__ float Rs[32][132];  // [d][k]
    __shared__ int   msk[8][128];  // [b][k]

    const int tid = threadIdx.x;
    const int tx = tid & 15;
    const int ty = tid >> 4;

    // mask tile: 8 b x 128 k = 1024 ints, 128 thr -> 8 each
    #pragma unroll
    for (int i = 0; i < 8; i++) {
        int s = tid + i * 128;
        msk[s >> 7][s & 127] = mask[(size_t)(s >> 7) * NKV + k0 + (s & 127)];
    }

    float acc[8][8];
    #pragma unroll
    for (int i = 0; i < 8; i++)
        #pragma unroll
        for (int j = 0; j < 8; j++) acc[i][j] = 0.f;

    #pragma unroll 1
    for (int d0 = 0; d0 < DH; d0 += 32) {
        // A: 64 bh rows x 8 float4 = 512 f4, 128 thr -> 4 each
        #pragma unroll
        for (int i = 0; i < 4; i++) {
            int s = tid + i * 128;
            int r = s >> 3;
            int c4 = (s & 7) * 4;
            float4 v = *(const float4*)&Q[(((size_t)r * NQ) + q) * DH + d0 + c4];
            Aqs[c4 + 0][r] = v.x; Aqs[c4 + 1][r] = v.y;
            Aqs[c4 + 2][r] = v.z; Aqs[c4 + 3][r] = v.w;
        }
        // R: 128 k rows x 8 float4 = 1024 f4, 128 thr -> 8 each
        #pragma unroll
        for (int i = 0; i < 8; i++) {
            int s = tid + i * 128;
            int r = s >> 3;
            int c4 = (s & 7) * 4;
            float4 w = *(const float4*)&R[(((size_t)q * NKV) + k0 + r) * DH + d0 + c4];
            Rs[c4 + 0][r] = w.x; Rs[c4 + 1][r] = w.y;
            Rs[c4 + 2][r] = w.z; Rs[c4 + 3][r] = w.w;
        }
        __syncthreads();

        #pragma unroll 8
        for (int dd = 0; dd < 32; dd++) {
            float a[8], b[8];
            *(float4*)&a[0] = *(const float4*)&Aqs[dd][ty * 8];
            *(float4*)&a[4] = *(const float4*)&Aqs[dd][ty * 8 + 4];
            *(float4*)&b[0] = *(const float4*)&Rs[dd][tx * 8];
            *(float4*)&b[4] = *(const float4*)&Rs[dd][tx * 8 + 4];
            #pragma unroll
            for (int i = 0; i < 8; i++)
                #pragma unroll
                for (int j = 0; j < 8; j++)
                    acc[i][j] += a[i] * b[j];
        }
        __syncthreads();
    }

    #pragma unroll
    for (int i = 0; i < 8; i++) {
        int bh = ty * 8 + i;
        int b = bh >> 3;
        size_t base = ((size_t)bh * NQ + q) * NKV + k0 + tx * 8;
        float sv[8];
        *(float4*)&sv[0] = *(const float4*)&S[base];
        *(float4*)&sv[4] = *(const float4*)&S[base + 4];
        float ov[8];
        #pragma unroll
        for (int j = 0; j < 8; j++) {
            int kk = tx * 8 + j;
            float v = (sv[j] + acc[i][j]) * SCALE;
            ov[j] = (msk[b][kk] != 0) ? v : -1e30f;
        }
        *(float4*)&S[base]     = *(float4*)&ov[0];
        *(float4*)&S[base + 4] = *(float4*)&ov[4];
    }
}

// ---------------------------------------------------------------------------
// Row softmax in place: one block (256 thr) per (bh,q) row of 1024.
// ---------------------------------------------------------------------------
__global__ __launch_bounds__(256) void softmax_kernel(float* __restrict__ S)
{
    const size_t row = blockIdx.x;
    float* p = S + row * NKV;
    const int tid = threadIdx.x;
    const int lane = tid & 31;
    const int warp = tid >> 5;

    __shared__ float red[8];

    float4 v = *(const float4*)&p[tid * 4];
    float m = fmaxf(fmaxf(v.x, v.y), fmaxf(v.z, v.w));
    #pragma unroll
    for (int o = 16; o > 0; o >>= 1)
        m = fmaxf(m, __shfl_xor_sync(0xFFFFFFFFu, m, o));
    if (lane == 0) red[warp] = m;
    __syncthreads();
    float M = red[0];
    #pragma unroll
    for (int w = 1; w < 8; w++) M = fmaxf(M, red[w]);
    __syncthreads();

    float e0 = __expf(v.x - M);
    float e1 = __expf(v.y - M);
    float e2 = __expf(v.z - M);
    float e3 = __expf(v.w - M);
    float s = e0 + e1 + e2 + e3;
    #pragma unroll
    for (int o = 16; o > 0; o >>= 1)
        s += __shfl_xor_sync(0xFFFFFFFFu, s, o);
    if (lane == 0) red[warp] = s;
    __syncthreads();
    float Sum = 0.f;
    #pragma unroll
    for (int w = 0; w < 8; w++) Sum += red[w];

    float inv = 1.f / Sum;
    float4 o4 = make_float4(e0 * inv, e1 * inv, e2 * inv, e3 * inv);
    *(float4*)&p[tid * 4] = o4;
}

// ---------------------------------------------------------------------------
// PV: ctx[b][q][h*64+d] = sum_k P[bh][q][k] * V[bh][k][d]
// Block: (q_tile 128, bh). 128x64 output, BK=32, 128 threads, 8x8/thread.
// ---------------------------------------------------------------------------
__global__ __launch_bounds__(128) void pv_kernel(
    const float* __restrict__ P, const float* __restrict__ V,
    float* __restrict__ ctx)
{
    const int bh = blockIdx.y;
    const int q0 = blockIdx.x * 128;
    const float* Pb = P + (size_t)bh * NQ * NKV;
    const float* Vb = V + (size_t)bh * NKV * DH;

    __shared__ float Ps[32][132]; // [k][q]
    __shared__ float Vs[32][68];  // [k][d]

    const int tid = threadIdx.x;
    const int tx = tid & 7;    // d: 8 x 8 = 64
    const int ty = tid >> 3;   // q: 16 x 8 = 128

    float acc[8][8];
    #pragma unroll
    for (int i = 0; i < 8; i++)
        #pragma unroll
        for (int j = 0; j < 8; j++) acc[i][j] = 0.f;

    #pragma unroll 1
    for (int k0 = 0; k0 < NKV; k0 += 32) {
        // P: 128 q rows x 8 float4 = 1024 f4, 128 thr -> 8 each (transposed store)
        #pragma unroll
        for (int i = 0; i < 8; i++) {
            int s = tid + i * 128;
            int r = s >> 3;
            int c4 = (s & 7) * 4;
            float4 v = *(const float4*)&Pb[(size_t)(q0 + r) * NKV + k0 + c4];
            Ps[c4 + 0][r] = v.x; Ps[c4 + 1][r] = v.y;
            Ps[c4 + 2][r] = v.z; Ps[c4 + 3][r] = v.w;
        }
        // V: 32 k rows x 16 float4 = 512 f4, 128 thr -> 4 each (direct store)
        #pragma unroll
        for (int i = 0; i < 4; i++) {
            int s = tid + i * 128;
            int r = s >> 4;
            int c4 = (s & 15) * 4;
            *(float4*)&Vs[r][c4] = *(const float4*)&Vb[(size_t)(k0 + r) * DH + c4];
        }
        __syncthreads();

        #pragma unroll 8
        for (int kk = 0; kk < 32; kk++) {
            float a[8], b[8];
            *(float4*)&a[0] = *(const float4*)&Ps[kk][ty * 8];
            *(float4*)&a[4] = *(const float4*)&Ps[kk][ty * 8 + 4];
            *(float4*)&b[0] = *(const float4*)&Vs[kk][tx * 8];
            *(float4*)&b[4] = *(const float4*)&Vs[kk][tx * 8 + 4];
            #pragma unroll
            for (int i = 0; i < 8; i++)
                #pragma unroll
                for (int j = 0; j < 8; j++)
                    acc[i][j] += a[i] * b[j];
        }
        __syncthreads();
    }

    const int b = bh >> 3, h = bh & 7;
    #pragma unroll
    for (int i = 0; i < 8; i++) {
        int q = q0 + ty * 8 + i;
        size_t base = ((size_t)(b * NQ + q)) * DMODEL + h * DH + tx * 8;
        *(float4*)&ctx[base]     = *(float4*)&acc[i][0];
        *(float4*)&ctx[base + 4] = *(float4*)&acc[i][4];
    }
}

// ---------------------------------------------------------------------------
extern "C" void kernel_launch(void* const* d_in, const int* in_sizes, int n_in,
                              void* d_out, int out_size)
{
    const float* q    = (const float*)d_in[0];
    const float* kv   = (const float*)d_in[1];
    const int*   mask = (const int*)  d_in[2];
    const float* Wq   = (const float*)d_in[3];
    const float* bq   = (const float*)d_in[4];
    const float* Wk   = (const float*)d_in[5];
    const float* bk   = (const float*)d_in[6];
    const float* Wv   = (const float*)d_in[7];
    const float* bv   = (const float*)d_in[8];
    const float* Wo   = (const float*)d_in[9];
    const float* bo   = (const float*)d_in[10];
    const float* R    = (const float*)d_in[11];

    float* out = (float*)d_out;
    const size_t out_elems  = (size_t)BATCH * NQ * DMODEL;       // 4,194,304
    const size_t attn_elems = (size_t)BH * NQ * NKV;             // 67,108,864

    // Resolve scratch addresses once (host-side statics; not stream ops)
    static float *Qp = nullptr, *Kp = nullptr, *Vp = nullptr, *ctx = nullptr, *fb = nullptr;
    if (!Qp) {
        cudaGetSymbolAddress((void**)&Qp,  g_Q);
        cudaGetSymbolAddress((void**)&Kp,  g_K);
        cudaGetSymbolAddress((void**)&Vp,  g_V);
        cudaGetSymbolAddress((void**)&ctx, g_ctx);
        cudaGetSymbolAddress((void**)&fb,  g_scores_fallback);
    }

    // scores buffer: attn region of d_out if present, else device scratch
    float* scores = ((size_t)out_size >= out_elems + attn_elems) ? (out + out_elems) : fb;

    const int M = BATCH * NQ;   // 8192
    dim3 gemm_grid(DMODEL / 128, M / 128);  // (4, 64)

    // 1-3: projections with [b,h,n,d] permuted store
    sgemm_kernel<<<gemm_grid, 256>>>(q,  Wq, bq, Qp, M, DMODEL, DMODEL, 1);
    sgemm_kernel<<<gemm_grid, 256>>>(kv, Wk, bk, Kp, M, DMODEL, DMODEL, 1);
    sgemm_kernel<<<gemm_grid, 256>>>(kv, Wv, bv, Vp, M, DMODEL, DMODEL, 1);

    // 4: S1 = Q K^T per bh (128x128 tiles)
    dim3 qk_grid(NKV / 128, NQ / 128, BH);  // (8,8,64)
    qk_kernel<<<qk_grid, 256>>>(Qp, Kp, scores);

    // 5: S = mask ? (S1 + Q·R) * scale : -1e30   (R read once, 64x bh reuse)
    dim3 rpe_grid(NKV / 128, NQ);           // (8,1024)
    rpe_bias_kernel<<<rpe_grid, 128>>>(Qp, R, mask, scores);

    // 6: softmax rows in place -> attn
    softmax_kernel<<<BH * NQ, 256>>>(scores);

    // 7: ctx = attn @ V, stored [b,q,h*64+d]
    dim3 pv_grid(NQ / 128, BH);             // (8,64)
    pv_kernel<<<pv_grid, 128>>>(scores, Vp, ctx);

    // 8: out = ctx @ Wo + bo
    sgemm_kernel<<<gemm_grid, 256>>>(ctx, Wo, bo, out, M, DMODEL, DMODEL, 0);
}

// round 7
// speedup vs baseline: 1.3090x; 1.1932x over previous
#include <cuda_runtime.h>
#include <cuda_bf16.h>
#include <mma.h>
#include <cstdint>
#include <cstddef>

using namespace nvcuda;

// Problem constants
#define BATCH 8
#define NQ 1024
#define NKV 1024
#define DMODEL 512
#define NH 8
#define DH 64
#define BH (BATCH*NH)          // 64
#define SCALE 0.125f           // DH^-0.5

// Scratch (allocation-free rule: __device__ globals)
__device__ float g_Q[(size_t)BH*NQ*DH];     // [bh][q][d]
__device__ float g_K[(size_t)BH*NKV*DH];    // [bh][k][d]
__device__ float g_V[(size_t)BH*NKV*DH];    // [bh][k][d]
__device__ float g_ctx[(size_t)BATCH*NQ*DMODEL]; // [b][q][h*64+d]
__device__ float g_scores_fallback[(size_t)BH*NQ*NKV]; // only if out buffer lacks attn region

// split one float4 into bf16 hi + lo pairs (hi at p, lo at q; 4 consecutive halfs)
__device__ __forceinline__ void cvt_split4(float4 v, __nv_bfloat16* hp, __nv_bfloat16* lp)
{
    __nv_bfloat16 h0 = __float2bfloat16(v.x), h1 = __float2bfloat16(v.y);
    __nv_bfloat16 h2 = __float2bfloat16(v.z), h3 = __float2bfloat16(v.w);
    __nv_bfloat162 p0; p0.x = h0; p0.y = h1;
    __nv_bfloat162 p1; p1.x = h2; p1.y = h3;
    *(__nv_bfloat162*)(hp)     = p0;
    *(__nv_bfloat162*)(hp + 2) = p1;
    __nv_bfloat162 l0, l1;
    l0.x = __float2bfloat16(v.x - __bfloat162float(h0));
    l0.y = __float2bfloat16(v.y - __bfloat162float(h1));
    l1.x = __float2bfloat16(v.z - __bfloat162float(h2));
    l1.y = __float2bfloat16(v.w - __bfloat162float(h3));
    *(__nv_bfloat162*)(lp)     = l0;
    *(__nv_bfloat162*)(lp + 2) = l1;
}

// ===========================================================================
// WMMA SGEMM (split-bf16 x3): C[8192,512] = A[8192,512] @ W[512,512] + bias
// Tile 128x128, BK=32, 256 thr (8 warps), warp tile 64x32.
// smem (dynamic): bf16 tiles (ldm 48 / 144 halfs, 32B-aligned frag ptrs),
// then f32 staging [128][136] for bias+permute epilogue.
// ===========================================================================
#define SG_LDA 48    // halfs (96B rows)
#define SG_LDB 144   // halfs (288B rows)
#define SG_AHI 0
#define SG_ALO 12288
#define SG_BHI 24576
#define SG_BLO 33792
#define SG_STG_LD 136  // floats
#define SG_SMEM 69632  // max(tiles 43008, staging 128*136*4)

__global__ __launch_bounds__(256) void sgemm_wmma_kernel(
    const float* __restrict__ A, const float* __restrict__ W,
    const float* __restrict__ bias, float* __restrict__ C, int permute)
{
    extern __shared__ __align__(256) char sm[];
    __nv_bfloat16* Ahi = (__nv_bfloat16*)(sm + SG_AHI);
    __nv_bfloat16* Alo = (__nv_bfloat16*)(sm + SG_ALO);
    __nv_bfloat16* Bhi = (__nv_bfloat16*)(sm + SG_BHI);
    __nv_bfloat16* Blo = (__nv_bfloat16*)(sm + SG_BLO);
    float* stg = (float*)sm;

    const int tid = threadIdx.x;
    const int wid = tid >> 5;
    const int wm = wid >> 2;       // 0..1 (64-row slab)
    const int wn = wid & 3;        // 0..3 (32-col slab)
    const int row0 = blockIdx.y * 128;
    const int col0 = blockIdx.x * 128;

    wmma::fragment<wmma::accumulator, 16, 16, 16, float> acc[4][2];
    #pragma unroll
    for (int i = 0; i < 4; i++)
        #pragma unroll
        for (int j = 0; j < 2; j++)
            wmma::fill_fragment(acc[i][j], 0.f);

    for (int k0 = 0; k0 < DMODEL; k0 += 32) {
        // A tile 128x32: 1024 float4, 4 per thread
        #pragma unroll
        for (int i = 0; i < 4; i++) {
            int s = tid + i * 256;
            int r = s >> 3;
            int c4 = (s & 7) * 4;
            float4 v = *(const float4*)&A[(size_t)(row0 + r) * DMODEL + k0 + c4];
            cvt_split4(v, &Ahi[r * SG_LDA + c4], &Alo[r * SG_LDA + c4]);
        }
        // B tile 32x128: 1024 float4, 4 per thread
        #pragma unroll
        for (int i = 0; i < 4; i++) {
            int s = tid + i * 256;
            int r = s >> 5;
            int c4 = (s & 31) * 4;
            float4 v = *(const float4*)&W[(size_t)(k0 + r) * DMODEL + col0 + c4];
            cvt_split4(v, &Bhi[r * SG_LDB + c4], &Blo[r * SG_LDB + c4]);
        }
        __syncthreads();

        #pragma unroll
        for (int ks = 0; ks < 32; ks += 16) {
            wmma::fragment<wmma::matrix_a, 16,16,16, __nv_bfloat16, wmma::row_major> ah[4], al[4];
            wmma::fragment<wmma::matrix_b, 16,16,16, __nv_bfloat16, wmma::row_major> bh2[2], bl2[2];
            #pragma unroll
            for (int i = 0; i < 4; i++) {
                int m0 = wm * 64 + i * 16;
                wmma::load_matrix_sync(ah[i], &Ahi[m0 * SG_LDA + ks], SG_LDA);
                wmma::load_matrix_sync(al[i], &Alo[m0 * SG_LDA + ks], SG_LDA);
            }
            #pragma unroll
            for (int j = 0; j < 2; j++) {
                int n0 = wn * 32 + j * 16;
                wmma::load_matrix_sync(bh2[j], &Bhi[ks * SG_LDB + n0], SG_LDB);
                wmma::load_matrix_sync(bl2[j], &Blo[ks * SG_LDB + n0], SG_LDB);
            }
            #pragma unroll
            for (int i = 0; i < 4; i++)
                #pragma unroll
                for (int j = 0; j < 2; j++) {
                    wmma::mma_sync(acc[i][j], ah[i], bh2[j], acc[i][j]);
                    wmma::mma_sync(acc[i][j], al[i], bh2[j], acc[i][j]);
                    wmma::mma_sync(acc[i][j], ah[i], bl2[j], acc[i][j]);
                }
        }
        __syncthreads();
    }

    // epilogue: frags -> staging -> bias add (+ optional permute) -> gmem
    #pragma unroll
    for (int i = 0; i < 4; i++)
        #pragma unroll
        for (int j = 0; j < 2; j++)
            wmma::store_matrix_sync(
                &stg[(wm * 64 + i * 16) * SG_STG_LD + wn * 32 + j * 16],
                acc[i][j], SG_STG_LD, wmma::mem_row_major);
    __syncthreads();

    #pragma unroll
    for (int i = 0; i < 16; i++) {
        int s = tid + i * 256;          // 4096 float4
        int r = s >> 5;
        int c4 = (s & 31) * 4;
        float4 v = *(float4*)&stg[r * SG_STG_LD + c4];
        int gc = col0 + c4;
        v.x += bias[gc]; v.y += bias[gc + 1]; v.z += bias[gc + 2]; v.w += bias[gc + 3];
        int gr = row0 + r;
        if (permute) {
            int b = gr >> 10, n = gr & 1023;
            int h = gc >> 6,  d = gc & 63;
            *(float4*)&C[(((size_t)(b * NH + h)) * NQ + n) * DH + d] = v;
        } else {
            *(float4*)&C[(size_t)gr * DMODEL + gc] = v;
        }
    }
}

// ===========================================================================
// WMMA QK^T (split-bf16 x3): S[bh][q][k] = sum_d Q[bh][q][d]*K[bh][k][d]
// Block: 128(q)x128(k) per bh, 256 thr, warp tile 64x32, d chunked by 32.
// ===========================================================================
#define QK_LD 48     // halfs
#define QK_QHI 0
#define QK_QLO 12288
#define QK_KHI 24576
#define QK_KLO 36864
#define QK_SMEM 49152

__global__ __launch_bounds__(256) void qk_wmma_kernel(
    const float* __restrict__ Q, const float* __restrict__ Km,
    float* __restrict__ S)
{
    extern __shared__ __align__(256) char sm[];
    __nv_bfloat16* Qhi = (__nv_bfloat16*)(sm + QK_QHI);
    __nv_bfloat16* Qlo = (__nv_bfloat16*)(sm + QK_QLO);
    __nv_bfloat16* Khi = (__nv_bfloat16*)(sm + QK_KHI);
    __nv_bfloat16* Klo = (__nv_bfloat16*)(sm + QK_KLO);

    const int bh = blockIdx.z;
    const int q0 = blockIdx.y * 128;
    const int k0 = blockIdx.x * 128;
    const float* Qb = Q + (size_t)bh * NQ * DH;
    const float* Kb = Km + (size_t)bh * NKV * DH;

    const int tid = threadIdx.x;
    const int wid = tid >> 5;
    const int wm = wid >> 2;       // q slab 64
    const int wn = wid & 3;        // k slab 32

    wmma::fragment<wmma::accumulator, 16, 16, 16, float> acc[4][2];
    #pragma unroll
    for (int i = 0; i < 4; i++)
        #pragma unroll
        for (int j = 0; j < 2; j++)
            wmma::fill_fragment(acc[i][j], 0.f);

    #pragma unroll
    for (int d0 = 0; d0 < DH; d0 += 32) {
        // Q/K tiles: 128 rows x 32 d each; 1024 f4 each; 4 f4/thread each
        #pragma unroll
        for (int i = 0; i < 4; i++) {
            int s = tid + i * 256;
            int r = s >> 3;
            int c4 = (s & 7) * 4;
            float4 v = *(const float4*)&Qb[(size_t)(q0 + r) * DH + d0 + c4];
            cvt_split4(v, &Qhi[r * QK_LD + c4], &Qlo[r * QK_LD + c4]);
            float4 w = *(const float4*)&Kb[(size_t)(k0 + r) * DH + d0 + c4];
            cvt_split4(w, &Khi[r * QK_LD + c4], &Klo[r * QK_LD + c4]);
        }
        __syncthreads();

        #pragma unroll
        for (int ks = 0; ks < 32; ks += 16) {
            wmma::fragment<wmma::matrix_a, 16,16,16, __nv_bfloat16, wmma::row_major> ah[4], al[4];
            wmma::fragment<wmma::matrix_b, 16,16,16, __nv_bfloat16, wmma::col_major> bh2[2], bl2[2];
            #pragma unroll
            for (int i = 0; i < 4; i++) {
                int m0 = wm * 64 + i * 16;
                wmma::load_matrix_sync(ah[i], &Qhi[m0 * QK_LD + ks], QK_LD);
                wmma::load_matrix_sync(al[i], &Qlo[m0 * QK_LD + ks], QK_LD);
            }
            #pragma unroll
            for (int j = 0; j < 2; j++) {
                int n0 = wn * 32 + j * 16;
                // col-major B: element (d, k) lives at k*QK_LD + d
                wmma::load_matrix_sync(bh2[j], &Khi[n0 * QK_LD + ks], QK_LD);
                wmma::load_matrix_sync(bl2[j], &Klo[n0 * QK_LD + ks], QK_LD);
            }
            #pragma unroll
            for (int i = 0; i < 4; i++)
                #pragma unroll
                for (int j = 0; j < 2; j++) {
                    wmma::mma_sync(acc[i][j], ah[i], bh2[j], acc[i][j]);
                    wmma::mma_sync(acc[i][j], al[i], bh2[j], acc[i][j]);
                    wmma::mma_sync(acc[i][j], ah[i], bl2[j], acc[i][j]);
                }
        }
        __syncthreads();
    }

    #pragma unroll
    for (int i = 0; i < 4; i++)
        #pragma unroll
        for (int j = 0; j < 2; j++)
            wmma::store_matrix_sync(
                &S[((size_t)bh * NQ + q0 + wm * 64 + i * 16) * NKV + k0 + wn * 32 + j * 16],
                acc[i][j], NKV, wmma::mem_row_major);
}

// ---------------------------------------------------------------------------
// RPE bias + scale + mask (in place on S)  (fp32, unchanged)
// ---------------------------------------------------------------------------
__global__ __launch_bounds__(128) void rpe_bias_kernel(
    const float* __restrict__ Q, const float* __restrict__ R,
    const int* __restrict__ mask, float* __restrict__ S)
{
    const int q  = blockIdx.y;
    const int k0 = blockIdx.x * 128;

    __shared__ float Aqs[32][68];  // [d][bh]
    __shared__ float Rs[32][132];  // [d][k]
    __shared__ int   msk[8][128];  // [b][k]

    const int tid = threadIdx.x;
    const int tx = tid & 15;
    const int ty = tid >> 4;

    #pragma unroll
    for (int i = 0; i < 8; i++) {
        int s = tid + i * 128;
        msk[s >> 7][s & 127] = mask[(size_t)(s >> 7) * NKV + k0 + (s & 127)];
    }

    float acc[8][8];
    #pragma unroll
    for (int i = 0; i < 8; i++)
        #pragma unroll
        for (int j = 0; j < 8; j++) acc[i][j] = 0.f;

    #pragma unroll 1
    for (int d0 = 0; d0 < DH; d0 += 32) {
        #pragma unroll
        for (int i = 0; i < 4; i++) {
            int s = tid + i * 128;
            int r = s >> 3;
            int c4 = (s & 7) * 4;
            float4 v = *(const float4*)&Q[(((size_t)r * NQ) + q) * DH + d0 + c4];
            Aqs[c4 + 0][r] = v.x; Aqs[c4 + 1][r] = v.y;
            Aqs[c4 + 2][r] = v.z; Aqs[c4 + 3][r] = v.w;
        }
        #pragma unroll
        for (int i = 0; i < 8; i++) {
            int s = tid + i * 128;
            int r = s >> 3;
            int c4 = (s & 7) * 4;
            float4 w = *(const float4*)&R[(((size_t)q * NKV) + k0 + r) * DH + d0 + c4];
            Rs[c4 + 0][r] = w.x; Rs[c4 + 1][r] = w.y;
            Rs[c4 + 2][r] = w.z; Rs[c4 + 3][r] = w.w;
        }
        __syncthreads();

        #pragma unroll 8
        for (int dd = 0; dd < 32; dd++) {
            float a[8], b[8];
            *(float4*)&a[0] = *(const float4*)&Aqs[dd][ty * 8];
            *(float4*)&a[4] = *(const float4*)&Aqs[dd][ty * 8 + 4];
            *(float4*)&b[0] = *(const float4*)&Rs[dd][tx * 8];
            *(float4*)&b[4] = *(const float4*)&Rs[dd][tx * 8 + 4];
            #pragma unroll
            for (int i = 0; i < 8; i++)
                #pragma unroll
                for (int j = 0; j < 8; j++)
                    acc[i][j] += a[i] * b[j];
        }
        __syncthreads();
    }

    #pragma unroll
    for (int i = 0; i < 8; i++) {
        int bh = ty * 8 + i;
        int b = bh >> 3;
        size_t base = ((size_t)bh * NQ + q) * NKV + k0 + tx * 8;
        float sv[8];
        *(float4*)&sv[0] = *(const float4*)&S[base];
        *(float4*)&sv[4] = *(const float4*)&S[base + 4];
        float ov[8];
        #pragma unroll
        for (int j = 0; j < 8; j++) {
            int kk = tx * 8 + j;
            float v = (sv[j] + acc[i][j]) * SCALE;
            ov[j] = (msk[b][kk] != 0) ? v : -1e30f;
        }
        *(float4*)&S[base]     = *(float4*)&ov[0];
        *(float4*)&S[base + 4] = *(float4*)&ov[4];
    }
}

// ---------------------------------------------------------------------------
// Row softmax in place  (unchanged)
// ---------------------------------------------------------------------------
__global__ __launch_bounds__(256) void softmax_kernel(float* __restrict__ S)
{
    const size_t row = blockIdx.x;
    float* p = S + row * NKV;
    const int tid = threadIdx.x;
    const int lane = tid & 31;
    const int warp = tid >> 5;

    __shared__ float red[8];

    float4 v = *(const float4*)&p[tid * 4];
    float m = fmaxf(fmaxf(v.x, v.y), fmaxf(v.z, v.w));
    #pragma unroll
    for (int o = 16; o > 0; o >>= 1)
        m = fmaxf(m, __shfl_xor_sync(0xFFFFFFFFu, m, o));
    if (lane == 0) red[warp] = m;
    __syncthreads();
    float M = red[0];
    #pragma unroll
    for (int w = 1; w < 8; w++) M = fmaxf(M, red[w]);
    __syncthreads();

    float e0 = __expf(v.x - M);
    float e1 = __expf(v.y - M);
    float e2 = __expf(v.z - M);
    float e3 = __expf(v.w - M);
    float s = e0 + e1 + e2 + e3;
    #pragma unroll
    for (int o = 16; o > 0; o >>= 1)
        s += __shfl_xor_sync(0xFFFFFFFFu, s, o);
    if (lane == 0) red[warp] = s;
    __syncthreads();
    float Sum = 0.f;
    #pragma unroll
    for (int w = 0; w < 8; w++) Sum += red[w];

    float inv = 1.f / Sum;
    float4 o4 = make_float4(e0 * inv, e1 * inv, e2 * inv, e3 * inv);
    *(float4*)&p[tid * 4] = o4;
}

// ---------------------------------------------------------------------------
// PV: ctx[b][q][h*64+d] = sum_k P[bh][q][k] * V[bh][k][d]  (fp32, unchanged)
// ---------------------------------------------------------------------------
__global__ __launch_bounds__(128) void pv_kernel(
    const float* __restrict__ P, const float* __restrict__ V,
    float* __restrict__ ctx)
{
    const int bh = blockIdx.y;
    const int q0 = blockIdx.x * 128;
    const float* Pb = P + (size_t)bh * NQ * NKV;
    const float* Vb = V + (size_t)bh * NKV * DH;

    __shared__ float Ps[32][132]; // [k][q]
    __shared__ float Vs[32][68];  // [k][d]

    const int tid = threadIdx.x;
    const int tx = tid & 7;    // d: 8 x 8 = 64
    const int ty = tid >> 3;   // q: 16 x 8 = 128

    float acc[8][8];
    #pragma unroll
    for (int i = 0; i < 8; i++)
        #pragma unroll
        for (int j = 0; j < 8; j++) acc[i][j] = 0.f;

    #pragma unroll 1
    for (int k0 = 0; k0 < NKV; k0 += 32) {
        #pragma unroll
        for (int i = 0; i < 8; i++) {
            int s = tid + i * 128;
            int r = s >> 3;
            int c4 = (s & 7) * 4;
            float4 v = *(const float4*)&Pb[(size_t)(q0 + r) * NKV + k0 + c4];
            Ps[c4 + 0][r] = v.x; Ps[c4 + 1][r] = v.y;
            Ps[c4 + 2][r] = v.z; Ps[c4 + 3][r] = v.w;
        }
        #pragma unroll
        for (int i = 0; i < 4; i++) {
            int s = tid + i * 128;
            int r = s >> 4;
            int c4 = (s & 15) * 4;
            *(float4*)&Vs[r][c4] = *(const float4*)&Vb[(size_t)(k0 + r) * DH + c4];
        }
        __syncthreads();

        #pragma unroll 8
        for (int kk = 0; kk < 32; kk++) {
            float a[8], b[8];
            *(float4*)&a[0] = *(const float4*)&Ps[kk][ty * 8];
            *(float4*)&a[4] = *(const float4*)&Ps[kk][ty * 8 + 4];
            *(float4*)&b[0] = *(const float4*)&Vs[kk][tx * 8];
            *(float4*)&b[4] = *(const float4*)&Vs[kk][tx * 8 + 4];
            #pragma unroll
            for (int i = 0; i < 8; i++)
                #pragma unroll
                for (int j = 0; j < 8; j++)
                    acc[i][j] += a[i] * b[j];
        }
        __syncthreads();
    }

    const int b = bh >> 3, h = bh & 7;
    #pragma unroll
    for (int i = 0; i < 8; i++) {
        int q = q0 + ty * 8 + i;
        size_t base = ((size_t)(b * NQ + q)) * DMODEL + h * DH + tx * 8;
        *(float4*)&ctx[base]     = *(float4*)&acc[i][0];
        *(float4*)&ctx[base + 4] = *(float4*)&acc[i][4];
    }
}

// ---------------------------------------------------------------------------
extern "C" void kernel_launch(void* const* d_in, const int* in_sizes, int n_in,
                              void* d_out, int out_size)
{
    const float* q    = (const float*)d_in[0];
    const float* kv   = (const float*)d_in[1];
    const int*   mask = (const int*)  d_in[2];
    const float* Wq   = (const float*)d_in[3];
    const float* bq   = (const float*)d_in[4];
    const float* Wk   = (const float*)d_in[5];
    const float* bk   = (const float*)d_in[6];
    const float* Wv   = (const float*)d_in[7];
    const float* bv   = (const float*)d_in[8];
    const float* Wo   = (const float*)d_in[9];
    const float* bo   = (const float*)d_in[10];
    const float* R    = (const float*)d_in[11];

    float* out = (float*)d_out;
    const size_t out_elems  = (size_t)BATCH * NQ * DMODEL;       // 4,194,304
    const size_t attn_elems = (size_t)BH * NQ * NKV;             // 67,108,864

    // Resolve scratch addresses + smem attrs once (host-side, first call)
    static float *Qp = nullptr, *Kp = nullptr, *Vp = nullptr, *ctx = nullptr, *fb = nullptr;
    if (!Qp) {
        cudaGetSymbolAddress((void**)&Qp,  g_Q);
        cudaGetSymbolAddress((void**)&Kp,  g_K);
        cudaGetSymbolAddress((void**)&Vp,  g_V);
        cudaGetSymbolAddress((void**)&ctx, g_ctx);
        cudaGetSymbolAddress((void**)&fb,  g_scores_fallback);
        cudaFuncSetAttribute(sgemm_wmma_kernel,
                             cudaFuncAttributeMaxDynamicSharedMemorySize, SG_SMEM);
        cudaFuncSetAttribute(qk_wmma_kernel,
                             cudaFuncAttributeMaxDynamicSharedMemorySize, QK_SMEM);
    }

    // scores buffer: attn region of d_out if present, else device scratch
    float* scores = ((size_t)out_size >= out_elems + attn_elems) ? (out + out_elems) : fb;

    const int M = BATCH * NQ;   // 8192
    dim3 gemm_grid(DMODEL / 128, M / 128);  // (4, 64)

    // 1-3: projections (WMMA split-bf16) with [b,h,n,d] permuted store
    sgemm_wmma_kernel<<<gemm_grid, 256, SG_SMEM>>>(q,  Wq, bq, Qp, 1);
    sgemm_wmma_kernel<<<gemm_grid, 256, SG_SMEM>>>(kv, Wk, bk, Kp, 1);
    sgemm_wmma_kernel<<<gemm_grid, 256, SG_SMEM>>>(kv, Wv, bv, Vp, 1);

    // 4: S1 = Q K^T per bh (WMMA split-bf16, 128x128 tiles)
    dim3 qk_grid(NKV / 128, NQ / 128, BH);  // (8,8,64)
    qk_wmma_kernel<<<qk_grid, 256, QK_SMEM>>>(Qp, Kp, scores);

    // 5: S = mask ? (S1 + Q·R) * scale : -1e30   (R read once, 64x bh reuse)
    dim3 rpe_grid(NKV / 128, NQ);           // (8,1024)
    rpe_bias_kernel<<<rpe_grid, 128>>>(Qp, R, mask, scores);

    // 6: softmax rows in place -> attn
    softmax_kernel<<<BH * NQ, 256>>>(scores);

    // 7: ctx = attn @ V, stored [b,q,h*64+d]
    dim3 pv_grid(NQ / 128, BH);             // (8,64)
    pv_kernel<<<pv_grid, 128>>>(scores, Vp, ctx);

    // 8: out = ctx @ Wo + bo (WMMA split-bf16)
    sgemm_wmma_kernel<<<gemm_grid, 256, SG_SMEM>>>(ctx, Wo, bo, out, 0);
}

// round 10
// speedup vs baseline: 1.6338x; 1.2481x over previous
#include <cuda_runtime.h>
#include <cuda_bf16.h>
#include <mma.h>
#include <cstdint>
#include <cstddef>

using namespace nvcuda;

// Problem constants
#define BATCH 8
#define NQ 1024
#define NKV 1024
#define DMODEL 512
#define NH 8
#define DH 64
#define BH (BATCH*NH)          // 64
#define SCALE 0.125f           // DH^-0.5

// Scratch (allocation-free rule: __device__ globals)
__device__ float g_Q[(size_t)BH*NQ*DH];     // [bh][q][d]
__device__ float g_K[(size_t)BH*NKV*DH];    // [bh][k][d]
__device__ float g_V[(size_t)BH*NKV*DH];    // [bh][k][d]
__device__ float g_ctx[(size_t)BATCH*NQ*DMODEL]; // [b][q][h*64+d]
__device__ float g_scores_fallback[(size_t)BH*NQ*NKV]; // only if out buffer lacks attn region

// split one float4 into bf16 hi + lo pairs (4 consecutive halfs each)
__device__ __forceinline__ void cvt_split4(float4 v, __nv_bfloat16* hp, __nv_bfloat16* lp)
{
    __nv_bfloat16 h0 = __float2bfloat16(v.x), h1 = __float2bfloat16(v.y);
    __nv_bfloat16 h2 = __float2bfloat16(v.z), h3 = __float2bfloat16(v.w);
    __nv_bfloat162 p0; p0.x = h0; p0.y = h1;
    __nv_bfloat162 p1; p1.x = h2; p1.y = h3;
    *(__nv_bfloat162*)(hp)     = p0;
    *(__nv_bfloat162*)(hp + 2) = p1;
    __nv_bfloat162 l0, l1;
    l0.x = __float2bfloat16(v.x - __bfloat162float(h0));
    l0.y = __float2bfloat16(v.y - __bfloat162float(h1));
    l1.x = __float2bfloat16(v.z - __bfloat162float(h2));
    l1.y = __float2bfloat16(v.w - __bfloat162float(h3));
    *(__nv_bfloat162*)(lp)     = l0;
    *(__nv_bfloat162*)(lp + 2) = l1;
}

// ===========================================================================
// WMMA SGEMM (split-bf16 x3): C[8192,512] = A[8192,512] @ W[512,512] + bias
// Tile 128x128, BK=32, 256 thr (8 warps), warp tile 64x32.
// ===========================================================================
#define SG_LDA 48    // halfs
#define SG_LDB 144   // halfs
#define SG_AHI 0
#define SG_ALO 12288
#define SG_BHI 24576
#define SG_BLO 33792
#define SG_STG_LD 136  // floats
#define SG_SMEM 69632

__global__ __launch_bounds__(256) void sgemm_wmma_kernel(
    const float* __restrict__ A, const float* __restrict__ W,
    const float* __restrict__ bias, float* __restrict__ C, int permute)
{
    extern __shared__ __align__(256) char sm[];
    __nv_bfloat16* Ahi = (__nv_bfloat16*)(sm + SG_AHI);
    __nv_bfloat16* Alo = (__nv_bfloat16*)(sm + SG_ALO);
    __nv_bfloat16* Bhi = (__nv_bfloat16*)(sm + SG_BHI);
    __nv_bfloat16* Blo = (__nv_bfloat16*)(sm + SG_BLO);
    float* stg = (float*)sm;

    const int tid = threadIdx.x;
    const int wid = tid >> 5;
    const int wm = wid >> 2;
    const int wn = wid & 3;
    const int row0 = blockIdx.y * 128;
    const int col0 = blockIdx.x * 128;

    wmma::fragment<wmma::accumulator, 16, 16, 16, float> acc[4][2];
    #pragma unroll
    for (int i = 0; i < 4; i++)
        #pragma unroll
        for (int j = 0; j < 2; j++)
            wmma::fill_fragment(acc[i][j], 0.f);

    for (int k0 = 0; k0 < DMODEL; k0 += 32) {
        #pragma unroll
        for (int i = 0; i < 4; i++) {
            int s = tid + i * 256;
            int r = s >> 3;
            int c4 = (s & 7) * 4;
            float4 v = *(const float4*)&A[(size_t)(row0 + r) * DMODEL + k0 + c4];
            cvt_split4(v, &Ahi[r * SG_LDA + c4], &Alo[r * SG_LDA + c4]);
        }
        #pragma unroll
        for (int i = 0; i < 4; i++) {
            int s = tid + i * 256;
            int r = s >> 5;
            int c4 = (s & 31) * 4;
            float4 v = *(const float4*)&W[(size_t)(k0 + r) * DMODEL + col0 + c4];
            cvt_split4(v, &Bhi[r * SG_LDB + c4], &Blo[r * SG_LDB + c4]);
        }
        __syncthreads();

        #pragma unroll
        for (int ks = 0; ks < 32; ks += 16) {
            wmma::fragment<wmma::matrix_a, 16,16,16, __nv_bfloat16, wmma::row_major> ah[4], al[4];
            wmma::fragment<wmma::matrix_b, 16,16,16, __nv_bfloat16, wmma::row_major> bh2[2], bl2[2];
            #pragma unroll
            for (int i = 0; i < 4; i++) {
                int m0 = wm * 64 + i * 16;
                wmma::load_matrix_sync(ah[i], &Ahi[m0 * SG_LDA + ks], SG_LDA);
                wmma::load_matrix_sync(al[i], &Alo[m0 * SG_LDA + ks], SG_LDA);
            }
            #pragma unroll
            for (int j = 0; j < 2; j++) {
                int n0 = wn * 32 + j * 16;
                wmma::load_matrix_sync(bh2[j], &Bhi[ks * SG_LDB + n0], SG_LDB);
                wmma::load_matrix_sync(bl2[j], &Blo[ks * SG_LDB + n0], SG_LDB);
            }
            #pragma unroll
            for (int i = 0; i < 4; i++)
                #pragma unroll
                for (int j = 0; j < 2; j++) {
                    wmma::mma_sync(acc[i][j], ah[i], bh2[j], acc[i][j]);
                    wmma::mma_sync(acc[i][j], al[i], bh2[j], acc[i][j]);
                    wmma::mma_sync(acc[i][j], ah[i], bl2[j], acc[i][j]);
                }
        }
        __syncthreads();
    }

    #pragma unroll
    for (int i = 0; i < 4; i++)
        #pragma unroll
        for (int j = 0; j < 2; j++)
            wmma::store_matrix_sync(
                &stg[(wm * 64 + i * 16) * SG_STG_LD + wn * 32 + j * 16],
                acc[i][j], SG_STG_LD, wmma::mem_row_major);
    __syncthreads();

    #pragma unroll
    for (int i = 0; i < 16; i++) {
        int s = tid + i * 256;
        int r = s >> 5;
        int c4 = (s & 31) * 4;
        float4 v = *(float4*)&stg[r * SG_STG_LD + c4];
        int gc = col0 + c4;
        v.x += bias[gc]; v.y += bias[gc + 1]; v.z += bias[gc + 2]; v.w += bias[gc + 3];
        int gr = row0 + r;
        if (permute) {
            int b = gr >> 10, n = gr & 1023;
            int h = gc >> 6,  d = gc & 63;
            *(float4*)&C[(((size_t)(b * NH + h)) * NQ + n) * DH + d] = v;
        } else {
            *(float4*)&C[(size_t)gr * DMODEL + gc] = v;
        }
    }
}

// ===========================================================================
// WMMA QK^T (split-bf16 x3): S[bh][q][k] = sum_d Q[bh][q][d]*K[bh][k][d]
// ===========================================================================
#define QK_LD 48
#define QK_QHI 0
#define QK_QLO 12288
#define QK_KHI 24576
#define QK_KLO 36864
#define QK_SMEM 49152

__global__ __launch_bounds__(256) void qk_wmma_kernel(
    const float* __restrict__ Q, const float* __restrict__ Km,
    float* __restrict__ S)
{
    extern __shared__ __align__(256) char sm[];
    __nv_bfloat16* Qhi = (__nv_bfloat16*)(sm + QK_QHI);
    __nv_bfloat16* Qlo = (__nv_bfloat16*)(sm + QK_QLO);
    __nv_bfloat16* Khi = (__nv_bfloat16*)(sm + QK_KHI);
    __nv_bfloat16* Klo = (__nv_bfloat16*)(sm + QK_KLO);

    const int bh = blockIdx.z;
    const int q0 = blockIdx.y * 128;
    const int k0 = blockIdx.x * 128;
    const float* Qb = Q + (size_t)bh * NQ * DH;
    const float* Kb = Km + (size_t)bh * NKV * DH;

    const int tid = threadIdx.x;
    const int wid = tid >> 5;
    const int wm = wid >> 2;
    const int wn = wid & 3;

    wmma::fragment<wmma::accumulator, 16, 16, 16, float> acc[4][2];
    #pragma unroll
    for (int i = 0; i < 4; i++)
        #pragma unroll
        for (int j = 0; j < 2; j++)
            wmma::fill_fragment(acc[i][j], 0.f);

    #pragma unroll
    for (int d0 = 0; d0 < DH; d0 += 32) {
        #pragma unroll
        for (int i = 0; i < 4; i++) {
            int s = tid + i * 256;
            int r = s >> 3;
            int c4 = (s & 7) * 4;
            float4 v = *(const float4*)&Qb[(size_t)(q0 + r) * DH + d0 + c4];
            cvt_split4(v, &Qhi[r * QK_LD + c4], &Qlo[r * QK_LD + c4]);
            float4 w = *(const float4*)&Kb[(size_t)(k0 + r) * DH + d0 + c4];
            cvt_split4(w, &Khi[r * QK_LD + c4], &Klo[r * QK_LD + c4]);
        }
        __syncthreads();

        #pragma unroll
        for (int ks = 0; ks < 32; ks += 16) {
            wmma::fragment<wmma::matrix_a, 16,16,16, __nv_bfloat16, wmma::row_major> ah[4], al[4];
            wmma::fragment<wmma::matrix_b, 16,16,16, __nv_bfloat16, wmma::col_major> bh2[2], bl2[2];
            #pragma unroll
            for (int i = 0; i < 4; i++) {
                int m0 = wm * 64 + i * 16;
                wmma::load_matrix_sync(ah[i], &Qhi[m0 * QK_LD + ks], QK_LD);
                wmma::load_matrix_sync(al[i], &Qlo[m0 * QK_LD + ks], QK_LD);
            }
            #pragma unroll
            for (int j = 0; j < 2; j++) {
                int n0 = wn * 32 + j * 16;
                wmma::load_matrix_sync(bh2[j], &Khi[n0 * QK_LD + ks], QK_LD);
                wmma::load_matrix_sync(bl2[j], &Klo[n0 * QK_LD + ks], QK_LD);
            }
            #pragma unroll
            for (int i = 0; i < 4; i++)
                #pragma unroll
                for (int j = 0; j < 2; j++) {
                    wmma::mma_sync(acc[i][j], ah[i], bh2[j], acc[i][j]);
                    wmma::mma_sync(acc[i][j], al[i], bh2[j], acc[i][j]);
                    wmma::mma_sync(acc[i][j], ah[i], bl2[j], acc[i][j]);
                }
        }
        __syncthreads();
    }

    #pragma unroll
    for (int i = 0; i < 4; i++)
        #pragma unroll
        for (int j = 0; j < 2; j++)
            wmma::store_matrix_sync(
                &S[((size_t)bh * NQ + q0 + wm * 64 + i * 16) * NKV + k0 + wn * 32 + j * 16],
                acc[i][j], NKV, wmma::mem_row_major);
}

// ===========================================================================
// WMMA RPE bias + scale + mask (in place on S):
//   S[bh][q][k] = mask[b][k] ? (S + sum_d Q[bh][q][d]*R[q][k][d]) * SCALE : -1e30
// Block per (q, k_tile 128): GEMM M=64(bh) x N=128(k) x K=64(d), 256 thr.
// Warp tile 32x32 (wm: 2 slabs of bh, wn: 4 slabs of k).
// ===========================================================================
#define RP_LD 80      // halfs (multiple of 16)
#define RP_QHI 0
#define RP_QLO 10240
#define RP_RHI 20480
#define RP_RLO 40960
#define RP_MSK 61440  // 1024 ints
#define RP_SMEM 65536
#define RP_STG_LD 136 // floats; staging overlaps [0, 34816) = dead Q/R-hi tiles

__global__ __launch_bounds__(256) void rpe_wmma_kernel(
    const float* __restrict__ Q, const float* __restrict__ R,
    const int* __restrict__ mask, float* __restrict__ S)
{
    extern __shared__ __align__(256) char sm[];
    __nv_bfloat16* Qhi = (__nv_bfloat16*)(sm + RP_QHI);
    __nv_bfloat16* Qlo = (__nv_bfloat16*)(sm + RP_QLO);
    __nv_bfloat16* Rhi = (__nv_bfloat16*)(sm + RP_RHI);
    __nv_bfloat16* Rlo = (__nv_bfloat16*)(sm + RP_RLO);
    int* msk = (int*)(sm + RP_MSK);
    float* stg = (float*)sm;

    const int q  = blockIdx.y;
    const int k0 = blockIdx.x * 128;
    const int tid = threadIdx.x;
    const int wid = tid >> 5;
    const int wm = wid >> 2;   // 0..1: 32-bh slab
    const int wn = wid & 3;    // 0..3: 32-k slab

    // mask tile: 8 b x 128 k = 1024 ints
    #pragma unroll
    for (int i = 0; i < 4; i++) {
        int s = tid + i * 256;
        msk[s] = mask[(size_t)(s >> 7) * NKV + k0 + (s & 127)];
    }
    // Q tile: 64 bh x 64 d (strided gather), 1024 f4
    #pragma unroll
    for (int i = 0; i < 4; i++) {
        int s = tid + i * 256;
        int r = s >> 4;
        int c4 = (s & 15) * 4;
        float4 v = *(const float4*)&Q[(((size_t)r * NQ) + q) * DH + c4];
        cvt_split4(v, &Qhi[r * RP_LD + c4], &Qlo[r * RP_LD + c4]);
    }
    // R tile: 128 k x 64 d, 2048 f4
    #pragma unroll
    for (int i = 0; i < 8; i++) {
        int s = tid + i * 256;
        int r = s >> 4;
        int c4 = (s & 15) * 4;
        float4 w = *(const float4*)&R[(((size_t)q * NKV) + k0 + r) * DH + c4];
        cvt_split4(w, &Rhi[r * RP_LD + c4], &Rlo[r * RP_LD + c4]);
    }
    __syncthreads();

    wmma::fragment<wmma::accumulator, 16, 16, 16, float> acc[2][2];
    #pragma unroll
    for (int i = 0; i < 2; i++)
        #pragma unroll
        for (int j = 0; j < 2; j++)
            wmma::fill_fragment(acc[i][j], 0.f);

    #pragma unroll
    for (int ks = 0; ks < 64; ks += 16) {
        wmma::fragment<wmma::matrix_a, 16,16,16, __nv_bfloat16, wmma::row_major> ah[2], al[2];
        wmma::fragment<wmma::matrix_b, 16,16,16, __nv_bfloat16, wmma::col_major> bh2[2], bl2[2];
        #pragma unroll
        for (int i = 0; i < 2; i++) {
            int m0 = wm * 32 + i * 16;
            wmma::load_matrix_sync(ah[i], &Qhi[m0 * RP_LD + ks], RP_LD);
            wmma::load_matrix_sync(al[i], &Qlo[m0 * RP_LD + ks], RP_LD);
        }
        #pragma unroll
        for (int j = 0; j < 2; j++) {
            int n0 = wn * 32 + j * 16;
            wmma::load_matrix_sync(bh2[j], &Rhi[n0 * RP_LD + ks], RP_LD);
            wmma::load_matrix_sync(bl2[j], &Rlo[n0 * RP_LD + ks], RP_LD);
        }
        #pragma unroll
        for (int i = 0; i < 2; i++)
            #pragma unroll
            for (int j = 0; j < 2; j++) {
                wmma::mma_sync(acc[i][j], ah[i], bh2[j], acc[i][j]);
                wmma::mma_sync(acc[i][j], al[i], bh2[j], acc[i][j]);
                wmma::mma_sync(acc[i][j], ah[i], bl2[j], acc[i][j]);
            }
    }
    __syncthreads();  // all tile reads done before staging overwrites

    #pragma unroll
    for (int i = 0; i < 2; i++)
        #pragma unroll
        for (int j = 0; j < 2; j++)
            wmma::store_matrix_sync(
                &stg[(wm * 32 + i * 16) * RP_STG_LD + wn * 32 + j * 16],
                acc[i][j], RP_STG_LD, wmma::mem_row_major);
    __syncthreads();

    // RMW epilogue: 64 bh x 128 k = 2048 f4, 8 per thread
    #pragma unroll
    for (int i = 0; i < 8; i++) {
        int s = tid + i * 256;
        int r = s >> 5;            // bh 0..63
        int c4 = (s & 31) * 4;     // k offset
        float4 bsv = *(float4*)&stg[r * RP_STG_LD + c4];
        size_t base = ((size_t)r * NQ + q) * NKV + k0 + c4;
        float4 sv = *(const float4*)&S[base];
        int b = r >> 3;
        float4 ov;
        ov.x = (msk[b * 128 + c4 + 0] != 0) ? (sv.x + bsv.x) * SCALE : -1e30f;
        ov.y = (msk[b * 128 + c4 + 1] != 0) ? (sv.y + bsv.y) * SCALE : -1e30f;
        ov.z = (msk[b * 128 + c4 + 2] != 0) ? (sv.z + bsv.z) * SCALE : -1e30f;
        ov.w = (msk[b * 128 + c4 + 3] != 0) ? (sv.w + bsv.w) * SCALE : -1e30f;
        *(float4*)&S[base] = ov;
    }
}

// ---------------------------------------------------------------------------
// Row softmax in place (unchanged)
// ---------------------------------------------------------------------------
__global__ __launch_bounds__(256) void softmax_kernel(float* __restrict__ S)
{
    const size_t row = blockIdx.x;
    float* p = S + row * NKV;
    const int tid = threadIdx.x;
    const int lane = tid & 31;
    const int warp = tid >> 5;

    __shared__ float red[8];

    float4 v = *(const float4*)&p[tid * 4];
    float m = fmaxf(fmaxf(v.x, v.y), fmaxf(v.z, v.w));
    #pragma unroll
    for (int o = 16; o > 0; o >>= 1)
        m = fmaxf(m, __shfl_xor_sync(0xFFFFFFFFu, m, o));
    if (lane == 0) red[warp] = m;
    __syncthreads();
    float M = red[0];
    #pragma unroll
    for (int w = 1; w < 8; w++) M = fmaxf(M, red[w]);
    __syncthreads();

    float e0 = __expf(v.x - M);
    float e1 = __expf(v.y - M);
    float e2 = __expf(v.z - M);
    float e3 = __expf(v.w - M);
    float s = e0 + e1 + e2 + e3;
    #pragma unroll
    for (int o = 16; o > 0; o >>= 1)
        s += __shfl_xor_sync(0xFFFFFFFFu, s, o);
    if (lane == 0) red[warp] = s;
    __syncthreads();
    float Sum = 0.f;
    #pragma unroll
    for (int w = 0; w < 8; w++) Sum += red[w];

    float inv = 1.f / Sum;
    float4 o4 = make_float4(e0 * inv, e1 * inv, e2 * inv, e3 * inv);
    *(float4*)&p[tid * 4] = o4;
}

// ===========================================================================
// WMMA PV (split-bf16 x3): ctx[b][q][h*64+d] = sum_k P[bh][q][k]*V[bh][k][d]
// Block per (q_tile 128, bh): M=128(q) x N=64(d) x K=1024, BK=64, 256 thr.
// Warp tile 32x32 (wm: 4 slabs of q, wn: 2 slabs of d). Direct frag store.
// ===========================================================================
#define PV_LD 80
#define PV_PHI 0
#define PV_PLO 20480
#define PV_VHI 40960
#define PV_VLO 51200
#define PV_SMEM 61440

__global__ __launch_bounds__(256) void pv_wmma_kernel(
    const float* __restrict__ P, const float* __restrict__ V,
    float* __restrict__ ctx)
{
    extern __shared__ __align__(256) char sm[];
    __nv_bfloat16* Phi = (__nv_bfloat16*)(sm + PV_PHI);
    __nv_bfloat16* Plo = (__nv_bfloat16*)(sm + PV_PLO);
    __nv_bfloat16* Vhi = (__nv_bfloat16*)(sm + PV_VHI);
    __nv_bfloat16* Vlo = (__nv_bfloat16*)(sm + PV_VLO);

    const int bh = blockIdx.y;
    const int q0 = blockIdx.x * 128;
    const float* Pb = P + (size_t)bh * NQ * NKV;
    const float* Vb = V + (size_t)bh * NKV * DH;

    const int tid = threadIdx.x;
    const int wid = tid >> 5;
    const int wm = wid >> 1;   // 0..3: 32-q slab
    const int wn = wid & 1;    // 0..1: 32-d slab

    wmma::fragment<wmma::accumulator, 16, 16, 16, float> acc[2][2];
    #pragma unroll
    for (int i = 0; i < 2; i++)
        #pragma unroll
        for (int j = 0; j < 2; j++)
            wmma::fill_fragment(acc[i][j], 0.f);

    #pragma unroll 1
    for (int k0 = 0; k0 < NKV; k0 += 64) {
        // P tile: 128 q x 64 k = 2048 f4, 8 per thread
        #pragma unroll
        for (int i = 0; i < 8; i++) {
            int s = tid + i * 256;
            int r = s >> 4;
            int c4 = (s & 15) * 4;
            float4 v = *(const float4*)&Pb[(size_t)(q0 + r) * NKV + k0 + c4];
            cvt_split4(v, &Phi[r * PV_LD + c4], &Plo[r * PV_LD + c4]);
        }
        // V tile: 64 k x 64 d = 1024 f4, 4 per thread
        #pragma unroll
        for (int i = 0; i < 4; i++) {
            int s = tid + i * 256;
            int r = s >> 4;
            int c4 = (s & 15) * 4;
            float4 w = *(const float4*)&Vb[(size_t)(k0 + r) * DH + c4];
            cvt_split4(w, &Vhi[r * PV_LD + c4], &Vlo[r * PV_LD + c4]);
        }
        __syncthreads();

        #pragma unroll
        for (int ks = 0; ks < 64; ks += 16) {
            wmma::fragment<wmma::matrix_a, 16,16,16, __nv_bfloat16, wmma::row_major> ah[2], al[2];
            wmma::fragment<wmma::matrix_b, 16,16,16, __nv_bfloat16, wmma::row_major> bh2[2], bl2[2];
            #pragma unroll
            for (int i = 0; i < 2; i++) {
                int m0 = wm * 32 + i * 16;
                wmma::load_matrix_sync(ah[i], &Phi[m0 * PV_LD + ks], PV_LD);
                wmma::load_matrix_sync(al[i], &Plo[m0 * PV_LD + ks], PV_LD);
            }
            #pragma unroll
            for (int j = 0; j < 2; j++) {
                int n0 = wn * 32 + j * 16;
                wmma::load_matrix_sync(bh2[j], &Vhi[ks * PV_LD + n0], PV_LD);
                wmma::load_matrix_sync(bl2[j], &Vlo[ks * PV_LD + n0], PV_LD);
            }
            #pragma unroll
            for (int i = 0; i < 2; i++)
                #pragma unroll
                for (int j = 0; j < 2; j++) {
                    wmma::mma_sync(acc[i][j], ah[i], bh2[j], acc[i][j]);
                    wmma::mma_sync(acc[i][j], al[i], bh2[j], acc[i][j]);
                    wmma::mma_sync(acc[i][j], ah[i], bl2[j], acc[i][j]);
                }
        }
        __syncthreads();
    }

    const int b = bh >> 3, h = bh & 7;
    #pragma unroll
    for (int i = 0; i < 2; i++)
        #pragma unroll
        for (int j = 0; j < 2; j++) {
            int qq = q0 + wm * 32 + i * 16;
            int dd = h * DH + wn * 32 + j * 16;
            wmma::store_matrix_sync(
                &ctx[((size_t)(b * NQ + qq)) * DMODEL + dd],
                acc[i][j], DMODEL, wmma::mem_row_major);
        }
}

// ---------------------------------------------------------------------------
extern "C" void kernel_launch(void* const* d_in, const int* in_sizes, int n_in,
                              void* d_out, int out_size)
{
    const float* q    = (const float*)d_in[0];
    const float* kv   = (const float*)d_in[1];
    const int*   mask = (const int*)  d_in[2];
    const float* Wq   = (const float*)d_in[3];
    const float* bq   = (const float*)d_in[4];
    const float* Wk   = (const float*)d_in[5];
    const float* bk   = (const float*)d_in[6];
    const float* Wv   = (const float*)d_in[7];
    const float* bv   = (const float*)d_in[8];
    const float* Wo   = (const float*)d_in[9];
    const float* bo   = (const float*)d_in[10];
    const float* R    = (const float*)d_in[11];

    float* out = (float*)d_out;
    const size_t out_elems  = (size_t)BATCH * NQ * DMODEL;       // 4,194,304
    const size_t attn_elems = (size_t)BH * NQ * NKV;             // 67,108,864

    static float *Qp = nullptr, *Kp = nullptr, *Vp = nullptr, *ctx = nullptr, *fb = nullptr;
    if (!Qp) {
        cudaGetSymbolAddress((void**)&Qp,  g_Q);
        cudaGetSymbolAddress((void**)&Kp,  g_K);
        cudaGetSymbolAddress((void**)&Vp,  g_V);
        cudaGetSymbolAddress((void**)&ctx, g_ctx);
        cudaGetSymbolAddress((void**)&fb,  g_scores_fallback);
        cudaFuncSetAttribute(sgemm_wmma_kernel,
                             cudaFuncAttributeMaxDynamicSharedMemorySize, SG_SMEM);
        cudaFuncSetAttribute(qk_wmma_kernel,
                             cudaFuncAttributeMaxDynamicSharedMemorySize, QK_SMEM);
        cudaFuncSetAttribute(rpe_wmma_kernel,
                             cudaFuncAttributeMaxDynamicSharedMemorySize, RP_SMEM);
        cudaFuncSetAttribute(pv_wmma_kernel,
                             cudaFuncAttributeMaxDynamicSharedMemorySize, PV_SMEM);
    }

    float* scores = ((size_t)out_size >= out_elems + attn_elems) ? (out + out_elems) : fb;

    const int M = BATCH * NQ;   // 8192
    dim3 gemm_grid(DMODEL / 128, M / 128);  // (4, 64)

    // 1-3: projections (WMMA split-bf16) with [b,h,n,d] permuted store
    sgemm_wmma_kernel<<<gemm_grid, 256, SG_SMEM>>>(q,  Wq, bq, Qp, 1);
    sgemm_wmma_kernel<<<gemm_grid, 256, SG_SMEM>>>(kv, Wk, bk, Kp, 1);
    sgemm_wmma_kernel<<<gemm_grid, 256, SG_SMEM>>>(kv, Wv, bv, Vp, 1);

    // 4: S1 = Q K^T per bh (WMMA)
    dim3 qk_grid(NKV / 128, NQ / 128, BH);  // (8,8,64)
    qk_wmma_kernel<<<qk_grid, 256, QK_SMEM>>>(Qp, Kp, scores);

    // 5: S = mask ? (S1 + Q·R) * scale : -1e30  (WMMA; R read once)
    dim3 rpe_grid(NKV / 128, NQ);           // (8,1024)
    rpe_wmma_kernel<<<rpe_grid, 256, RP_SMEM>>>(Qp, R, mask, scores);

    // 6: softmax rows in place -> attn
    softmax_kernel<<<BH * NQ, 256>>>(scores);

    // 7: ctx = attn @ V (WMMA), stored [b,q,h*64+d]
    dim3 pv_grid(NQ / 128, BH);             // (8,64)
    pv_wmma_kernel<<<pv_grid, 256, PV_SMEM>>>(scores, Vp, ctx);

    // 8: out = ctx @ Wo + bo (WMMA)
    sgemm_wmma_kernel<<<gemm_grid, 256, SG_SMEM>>>(ctx, Wo, bo, out, 0);
}

// round 11
// speedup vs baseline: 1.7329x; 1.0607x over previous
#include <cuda_runtime.h>
#include <cuda_bf16.h>
#include <mma.h>
#include <cstdint>
#include <cstddef>

using namespace nvcuda;

// Problem constants
#define BATCH 8
#define NQ 1024
#define NKV 1024
#define DMODEL 512
#define NH 8
#define DH 64
#define BH (BATCH*NH)          // 64
#define SCALE 0.125f           // DH^-0.5

// Scratch (allocation-free rule: __device__ globals)
__device__ float g_Q[(size_t)BH*NQ*DH];     // [bh][q][d]
__device__ float g_K[(size_t)BH*NKV*DH];    // [bh][k][d]
__device__ float g_V[(size_t)BH*NKV*DH];    // [bh][k][d]
__device__ float g_ctx[(size_t)BATCH*NQ*DMODEL]; // [b][q][h*64+d]
__device__ float g_scores_fallback[(size_t)BH*NQ*NKV]; // only if out buffer lacks attn region

// split one float4 into bf16 hi + lo pairs (4 consecutive halfs each)
__device__ __forceinline__ void cvt_split4(float4 v, __nv_bfloat16* hp, __nv_bfloat16* lp)
{
    __nv_bfloat16 h0 = __float2bfloat16(v.x), h1 = __float2bfloat16(v.y);
    __nv_bfloat16 h2 = __float2bfloat16(v.z), h3 = __float2bfloat16(v.w);
    __nv_bfloat162 p0; p0.x = h0; p0.y = h1;
    __nv_bfloat162 p1; p1.x = h2; p1.y = h3;
    *(__nv_bfloat162*)(hp)     = p0;
    *(__nv_bfloat162*)(hp + 2) = p1;
    __nv_bfloat162 l0, l1;
    l0.x = __float2bfloat16(v.x - __bfloat162float(h0));
    l0.y = __float2bfloat16(v.y - __bfloat162float(h1));
    l1.x = __float2bfloat16(v.z - __bfloat162float(h2));
    l1.y = __float2bfloat16(v.w - __bfloat162float(h3));
    *(__nv_bfloat162*)(lp)     = l0;
    *(__nv_bfloat162*)(lp + 2) = l1;
}

// ===========================================================================
// WMMA SGEMM (split-bf16 x3): C[8192,512] = A[8192,512] @ W[512,512] + bias
// Tile 64x128, BK=32, 256 thr (8 warps), warp tile 32x32, 2 CTAs/SM.
// ===========================================================================
#define SG_LDA 48    // halfs
#define SG_LDB 144   // halfs
#define SG_AHI 0
#define SG_ALO 6144
#define SG_BHI 12288
#define SG_BLO 21504
#define SG_STG_LD 136  // floats
#define SG_SMEM 34816  // max(tiles 30720, staging 64*136*4)

__global__ __launch_bounds__(256, 2) void sgemm_wmma_kernel(
    const float* __restrict__ A, const float* __restrict__ W,
    const float* __restrict__ bias, float* __restrict__ C, int permute)
{
    extern __shared__ __align__(256) char sm[];
    __nv_bfloat16* Ahi = (__nv_bfloat16*)(sm + SG_AHI);
    __nv_bfloat16* Alo = (__nv_bfloat16*)(sm + SG_ALO);
    __nv_bfloat16* Bhi = (__nv_bfloat16*)(sm + SG_BHI);
    __nv_bfloat16* Blo = (__nv_bfloat16*)(sm + SG_BLO);
    float* stg = (float*)sm;

    const int tid = threadIdx.x;
    const int wid = tid >> 5;
    const int wm = wid >> 2;       // 0..1: 32-row slab
    const int wn = wid & 3;        // 0..3: 32-col slab
    const int row0 = blockIdx.y * 64;
    const int col0 = blockIdx.x * 128;

    wmma::fragment<wmma::accumulator, 16, 16, 16, float> acc[2][2];
    #pragma unroll
    for (int i = 0; i < 2; i++)
        #pragma unroll
        for (int j = 0; j < 2; j++)
            wmma::fill_fragment(acc[i][j], 0.f);

    for (int k0 = 0; k0 < DMODEL; k0 += 32) {
        // A tile 64x32: 512 f4, 2 per thread
        #pragma unroll
        for (int i = 0; i < 2; i++) {
            int s = tid + i * 256;
            int r = s >> 3;
            int c4 = (s & 7) * 4;
            float4 v = *(const float4*)&A[(size_t)(row0 + r) * DMODEL + k0 + c4];
            cvt_split4(v, &Ahi[r * SG_LDA + c4], &Alo[r * SG_LDA + c4]);
        }
        // B tile 32x128: 1024 f4, 4 per thread
        #pragma unroll
        for (int i = 0; i < 4; i++) {
            int s = tid + i * 256;
            int r = s >> 5;
            int c4 = (s & 31) * 4;
            float4 v = *(const float4*)&W[(size_t)(k0 + r) * DMODEL + col0 + c4];
            cvt_split4(v, &Bhi[r * SG_LDB + c4], &Blo[r * SG_LDB + c4]);
        }
        __syncthreads();

        #pragma unroll
        for (int ks = 0; ks < 32; ks += 16) {
            wmma::fragment<wmma::matrix_a, 16,16,16, __nv_bfloat16, wmma::row_major> ah[2], al[2];
            wmma::fragment<wmma::matrix_b, 16,16,16, __nv_bfloat16, wmma::row_major> bh2[2], bl2[2];
            #pragma unroll
            for (int i = 0; i < 2; i++) {
                int m0 = wm * 32 + i * 16;
                wmma::load_matrix_sync(ah[i], &Ahi[m0 * SG_LDA + ks], SG_LDA);
                wmma::load_matrix_sync(al[i], &Alo[m0 * SG_LDA + ks], SG_LDA);
            }
            #pragma unroll
            for (int j = 0; j < 2; j++) {
                int n0 = wn * 32 + j * 16;
                wmma::load_matrix_sync(bh2[j], &Bhi[ks * SG_LDB + n0], SG_LDB);
                wmma::load_matrix_sync(bl2[j], &Blo[ks * SG_LDB + n0], SG_LDB);
            }
            #pragma unroll
            for (int i = 0; i < 2; i++)
                #pragma unroll
                for (int j = 0; j < 2; j++) {
                    wmma::mma_sync(acc[i][j], ah[i], bh2[j], acc[i][j]);
                    wmma::mma_sync(acc[i][j], al[i], bh2[j], acc[i][j]);
                    wmma::mma_sync(acc[i][j], ah[i], bl2[j], acc[i][j]);
                }
        }
        __syncthreads();
    }

    #pragma unroll
    for (int i = 0; i < 2; i++)
        #pragma unroll
        for (int j = 0; j < 2; j++)
            wmma::store_matrix_sync(
                &stg[(wm * 32 + i * 16) * SG_STG_LD + wn * 32 + j * 16],
                acc[i][j], SG_STG_LD, wmma::mem_row_major);
    __syncthreads();

    // 64x128 = 2048 f4, 8 per thread
    #pragma unroll
    for (int i = 0; i < 8; i++) {
        int s = tid + i * 256;
        int r = s >> 5;
        int c4 = (s & 31) * 4;
        float4 v = *(float4*)&stg[r * SG_STG_LD + c4];
        int gc = col0 + c4;
        v.x += bias[gc]; v.y += bias[gc + 1]; v.z += bias[gc + 2]; v.w += bias[gc + 3];
        int gr = row0 + r;
        if (permute) {
            int b = gr >> 10, n = gr & 1023;
            int h = gc >> 6,  d = gc & 63;
            *(float4*)&C[(((size_t)(b * NH + h)) * NQ + n) * DH + d] = v;
        } else {
            *(float4*)&C[(size_t)gr * DMODEL + gc] = v;
        }
    }
}

// ===========================================================================
// WMMA QK^T (split-bf16 x3): S[bh][q][k] = sum_d Q[bh][q][d]*K[bh][k][d]
// Tile 64(q)x128(k), full d=64 staged once, 256 thr, warp 32x32, 2 CTAs/SM.
// ===========================================================================
#define QK_LD 80     // halfs (d=64 padded)
#define QK_QHI 0
#define QK_QLO 10240
#define QK_KHI 20480
#define QK_KLO 40960
#define QK_SMEM 61440

__global__ __launch_bounds__(256, 2) void qk_wmma_kernel(
    const float* __restrict__ Q, const float* __restrict__ Km,
    float* __restrict__ S)
{
    extern __shared__ __align__(256) char sm[];
    __nv_bfloat16* Qhi = (__nv_bfloat16*)(sm + QK_QHI);
    __nv_bfloat16* Qlo = (__nv_bfloat16*)(sm + QK_QLO);
    __nv_bfloat16* Khi = (__nv_bfloat16*)(sm + QK_KHI);
    __nv_bfloat16* Klo = (__nv_bfloat16*)(sm + QK_KLO);

    const int bh = blockIdx.z;
    const int q0 = blockIdx.y * 64;
    const int k0 = blockIdx.x * 128;
    const float* Qb = Q + (size_t)bh * NQ * DH;
    const float* Kb = Km + (size_t)bh * NKV * DH;

    const int tid = threadIdx.x;
    const int wid = tid >> 5;
    const int wm = wid >> 2;   // 0..1: 32-q slab
    const int wn = wid & 3;    // 0..3: 32-k slab

    // Q tile: 64 q x 64 d = 1024 f4, 4 per thread
    #pragma unroll
    for (int i = 0; i < 4; i++) {
        int s = tid + i * 256;
        int r = s >> 4;
        int c4 = (s & 15) * 4;
        float4 v = *(const float4*)&Qb[(size_t)(q0 + r) * DH + c4];
        cvt_split4(v, &Qhi[r * QK_LD + c4], &Qlo[r * QK_LD + c4]);
    }
    // K tile: 128 k x 64 d = 2048 f4, 8 per thread
    #pragma unroll
    for (int i = 0; i < 8; i++) {
        int s = tid + i * 256;
        int r = s >> 4;
        int c4 = (s & 15) * 4;
        float4 w = *(const float4*)&Kb[(size_t)(k0 + r) * DH + c4];
        cvt_split4(w, &Khi[r * QK_LD + c4], &Klo[r * QK_LD + c4]);
    }
    __syncthreads();

    wmma::fragment<wmma::accumulator, 16, 16, 16, float> acc[2][2];
    #pragma unroll
    for (int i = 0; i < 2; i++)
        #pragma unroll
        for (int j = 0; j < 2; j++)
            wmma::fill_fragment(acc[i][j], 0.f);

    #pragma unroll
    for (int ks = 0; ks < DH; ks += 16) {
        wmma::fragment<wmma::matrix_a, 16,16,16, __nv_bfloat16, wmma::row_major> ah[2], al[2];
        wmma::fragment<wmma::matrix_b, 16,16,16, __nv_bfloat16, wmma::col_major> bh2[2], bl2[2];
        #pragma unroll
        for (int i = 0; i < 2; i++) {
            int m0 = wm * 32 + i * 16;
            wmma::load_matrix_sync(ah[i], &Qhi[m0 * QK_LD + ks], QK_LD);
            wmma::load_matrix_sync(al[i], &Qlo[m0 * QK_LD + ks], QK_LD);
        }
        #pragma unroll
        for (int j = 0; j < 2; j++) {
            int n0 = wn * 32 + j * 16;
            wmma::load_matrix_sync(bh2[j], &Khi[n0 * QK_LD + ks], QK_LD);
            wmma::load_matrix_sync(bl2[j], &Klo[n0 * QK_LD + ks], QK_LD);
        }
        #pragma unroll
        for (int i = 0; i < 2; i++)
            #pragma unroll
            for (int j = 0; j < 2; j++) {
                wmma::mma_sync(acc[i][j], ah[i], bh2[j], acc[i][j]);
                wmma::mma_sync(acc[i][j], al[i], bh2[j], acc[i][j]);
                wmma::mma_sync(acc[i][j], ah[i], bl2[j], acc[i][j]);
            }
    }

    #pragma unroll
    for (int i = 0; i < 2; i++)
        #pragma unroll
        for (int j = 0; j < 2; j++)
            wmma::store_matrix_sync(
                &S[((size_t)bh * NQ + q0 + wm * 32 + i * 16) * NKV + k0 + wn * 32 + j * 16],
                acc[i][j], NKV, wmma::mem_row_major);
}

// ===========================================================================
// WMMA RPE bias + scale + mask (in place on S) — unchanged from R10
// ===========================================================================
#define RP_LD 80      // halfs (multiple of 16)
#define RP_QHI 0
#define RP_QLO 10240
#define RP_RHI 20480
#define RP_RLO 40960
#define RP_MSK 61440  // 1024 ints
#define RP_SMEM 65536
#define RP_STG_LD 136 // floats; staging overlaps [0, 34816) = dead Q/R-hi tiles

__global__ __launch_bounds__(256) void rpe_wmma_kernel(
    const float* __restrict__ Q, const float* __restrict__ R,
    const int* __restrict__ mask, float* __restrict__ S)
{
    extern __shared__ __align__(256) char sm[];
    __nv_bfloat16* Qhi = (__nv_bfloat16*)(sm + RP_QHI);
    __nv_bfloat16* Qlo = (__nv_bfloat16*)(sm + RP_QLO);
    __nv_bfloat16* Rhi = (__nv_bfloat16*)(sm + RP_RHI);
    __nv_bfloat16* Rlo = (__nv_bfloat16*)(sm + RP_RLO);
    int* msk = (int*)(sm + RP_MSK);
    float* stg = (float*)sm;

    const int q  = blockIdx.y;
    const int k0 = blockIdx.x * 128;
    const int tid = threadIdx.x;
    const int wid = tid >> 5;
    const int wm = wid >> 2;   // 0..1: 32-bh slab
    const int wn = wid & 3;    // 0..3: 32-k slab

    #pragma unroll
    for (int i = 0; i < 4; i++) {
        int s = tid + i * 256;
        msk[s] = mask[(size_t)(s >> 7) * NKV + k0 + (s & 127)];
    }
    #pragma unroll
    for (int i = 0; i < 4; i++) {
        int s = tid + i * 256;
        int r = s >> 4;
        int c4 = (s & 15) * 4;
        float4 v = *(const float4*)&Q[(((size_t)r * NQ) + q) * DH + c4];
        cvt_split4(v, &Qhi[r * RP_LD + c4], &Qlo[r * RP_LD + c4]);
    }
    #pragma unroll
    for (int i = 0; i < 8; i++) {
        int s = tid + i * 256;
        int r = s >> 4;
        int c4 = (s & 15) * 4;
        float4 w = *(const float4*)&R[(((size_t)q * NKV) + k0 + r) * DH + c4];
        cvt_split4(w, &Rhi[r * RP_LD + c4], &Rlo[r * RP_LD + c4]);
    }
    __syncthreads();

    wmma::fragment<wmma::accumulator, 16, 16, 16, float> acc[2][2];
    #pragma unroll
    for (int i = 0; i < 2; i++)
        #pragma unroll
        for (int j = 0; j < 2; j++)
            wmma::fill_fragment(acc[i][j], 0.f);

    #pragma unroll
    for (int ks = 0; ks < 64; ks += 16) {
        wmma::fragment<wmma::matrix_a, 16,16,16, __nv_bfloat16, wmma::row_major> ah[2], al[2];
        wmma::fragment<wmma::matrix_b, 16,16,16, __nv_bfloat16, wmma::col_major> bh2[2], bl2[2];
        #pragma unroll
        for (int i = 0; i < 2; i++) {
            int m0 = wm * 32 + i * 16;
            wmma::load_matrix_sync(ah[i], &Qhi[m0 * RP_LD + ks], RP_LD);
            wmma::load_matrix_sync(al[i], &Qlo[m0 * RP_LD + ks], RP_LD);
        }
        #pragma unroll
        for (int j = 0; j < 2; j++) {
            int n0 = wn * 32 + j * 16;
            wmma::load_matrix_sync(bh2[j], &Rhi[n0 * RP_LD + ks], RP_LD);
            wmma::load_matrix_sync(bl2[j], &Rlo[n0 * RP_LD + ks], RP_LD);
        }
        #pragma unroll
        for (int i = 0; i < 2; i++)
            #pragma unroll
            for (int j = 0; j < 2; j++) {
                wmma::mma_sync(acc[i][j], ah[i], bh2[j], acc[i][j]);
                wmma::mma_sync(acc[i][j], al[i], bh2[j], acc[i][j]);
                wmma::mma_sync(acc[i][j], ah[i], bl2[j], acc[i][j]);
            }
    }
    __syncthreads();

    #pragma unroll
    for (int i = 0; i < 2; i++)
        #pragma unroll
        for (int j = 0; j < 2; j++)
            wmma::store_matrix_sync(
                &stg[(wm * 32 + i * 16) * RP_STG_LD + wn * 32 + j * 16],
                acc[i][j], RP_STG_LD, wmma::mem_row_major);
    __syncthreads();

    #pragma unroll
    for (int i = 0; i < 8; i++) {
        int s = tid + i * 256;
        int r = s >> 5;
        int c4 = (s & 31) * 4;
        float4 bsv = *(float4*)&stg[r * RP_STG_LD + c4];
        size_t base = ((size_t)r * NQ + q) * NKV + k0 + c4;
        float4 sv = *(const float4*)&S[base];
        int b = r >> 3;
        float4 ov;
        ov.x = (msk[b * 128 + c4 + 0] != 0) ? (sv.x + bsv.x) * SCALE : -1e30f;
        ov.y = (msk[b * 128 + c4 + 1] != 0) ? (sv.y + bsv.y) * SCALE : -1e30f;
        ov.z = (msk[b * 128 + c4 + 2] != 0) ? (sv.z + bsv.z) * SCALE : -1e30f;
        ov.w = (msk[b * 128 + c4 + 3] != 0) ? (sv.w + bsv.w) * SCALE : -1e30f;
        *(float4*)&S[base] = ov;
    }
}

// ---------------------------------------------------------------------------
// Row softmax in place (unchanged)
// ---------------------------------------------------------------------------
__global__ __launch_bounds__(256) void softmax_kernel(float* __restrict__ S)
{
    const size_t row = blockIdx.x;
    float* p = S + row * NKV;
    const int tid = threadIdx.x;
    const int lane = tid & 31;
    const int warp = tid >> 5;

    __shared__ float red[8];

    float4 v = *(const float4*)&p[tid * 4];
    float m = fmaxf(fmaxf(v.x, v.y), fmaxf(v.z, v.w));
    #pragma unroll
    for (int o = 16; o > 0; o >>= 1)
        m = fmaxf(m, __shfl_xor_sync(0xFFFFFFFFu, m, o));
    if (lane == 0) red[warp] = m;
    __syncthreads();
    float M = red[0];
    #pragma unroll
    for (int w = 1; w < 8; w++) M = fmaxf(M, red[w]);
    __syncthreads();

    float e0 = __expf(v.x - M);
    float e1 = __expf(v.y - M);
    float e2 = __expf(v.z - M);
    float e3 = __expf(v.w - M);
    float s = e0 + e1 + e2 + e3;
    #pragma unroll
    for (int o = 16; o > 0; o >>= 1)
        s += __shfl_xor_sync(0xFFFFFFFFu, s, o);
    if (lane == 0) red[warp] = s;
    __syncthreads();
    float Sum = 0.f;
    #pragma unroll
    for (int w = 0; w < 8; w++) Sum += red[w];

    float inv = 1.f / Sum;
    float4 o4 = make_float4(e0 * inv, e1 * inv, e2 * inv, e3 * inv);
    *(float4*)&p[tid * 4] = o4;
}

// ===========================================================================
// WMMA PV (split-bf16 x3) — unchanged from R10
// ===========================================================================
#define PV_LD 80
#define PV_PHI 0
#define PV_PLO 20480
#define PV_VHI 40960
#define PV_VLO 51200
#define PV_SMEM 61440

__global__ __launch_bounds__(256) void pv_wmma_kernel(
    const float* __restrict__ P, const float* __restrict__ V,
    float* __restrict__ ctx)
{
    extern __shared__ __align__(256) char sm[];
    __nv_bfloat16* Phi = (__nv_bfloat16*)(sm + PV_PHI);
    __nv_bfloat16* Plo = (__nv_bfloat16*)(sm + PV_PLO);
    __nv_bfloat16* Vhi = (__nv_bfloat16*)(sm + PV_VHI);
    __nv_bfloat16* Vlo = (__nv_bfloat16*)(sm + PV_VLO);

    const int bh = blockIdx.y;
    const int q0 = blockIdx.x * 128;
    const float* Pb = P + (size_t)bh * NQ * NKV;
    const float* Vb = V + (size_t)bh * NKV * DH;

    const int tid = threadIdx.x;
    const int wid = tid >> 5;
    const int wm = wid >> 1;   // 0..3: 32-q slab
    const int wn = wid & 1;    // 0..1: 32-d slab

    wmma::fragment<wmma::accumulator, 16, 16, 16, float> acc[2][2];
    #pragma unroll
    for (int i = 0; i < 2; i++)
        #pragma unroll
        for (int j = 0; j < 2; j++)
            wmma::fill_fragment(acc[i][j], 0.f);

    #pragma unroll 1
    for (int k0 = 0; k0 < NKV; k0 += 64) {
        #pragma unroll
        for (int i = 0; i < 8; i++) {
            int s = tid + i * 256;
            int r = s >> 4;
            int c4 = (s & 15) * 4;
            float4 v = *(const float4*)&Pb[(size_t)(q0 + r) * NKV + k0 + c4];
            cvt_split4(v, &Phi[r * PV_LD + c4], &Plo[r * PV_LD + c4]);
        }
        #pragma unroll
        for (int i = 0; i < 4; i++) {
            int s = tid + i * 256;
            int r = s >> 4;
            int c4 = (s & 15) * 4;
            float4 w = *(const float4*)&Vb[(size_t)(k0 + r) * DH + c4];
            cvt_split4(w, &Vhi[r * PV_LD + c4], &Vlo[r * PV_LD + c4]);
        }
        __syncthreads();

        #pragma unroll
        for (int ks = 0; ks < 64; ks += 16) {
            wmma::fragment<wmma::matrix_a, 16,16,16, __nv_bfloat16, wmma::row_major> ah[2], al[2];
            wmma::fragment<wmma::matrix_b, 16,16,16, __nv_bfloat16, wmma::row_major> bh2[2], bl2[2];
            #pragma unroll
            for (int i = 0; i < 2; i++) {
                int m0 = wm * 32 + i * 16;
                wmma::load_matrix_sync(ah[i], &Phi[m0 * PV_LD + ks], PV_LD);
                wmma::load_matrix_sync(al[i], &Plo[m0 * PV_LD + ks], PV_LD);
            }
            #pragma unroll
            for (int j = 0; j < 2; j++) {
                int n0 = wn * 32 + j * 16;
                wmma::load_matrix_sync(bh2[j], &Vhi[ks * PV_LD + n0], PV_LD);
                wmma::load_matrix_sync(bl2[j], &Vlo[ks * PV_LD + n0], PV_LD);
            }
            #pragma unroll
            for (int i = 0; i < 2; i++)
                #pragma unroll
                for (int j = 0; j < 2; j++) {
                    wmma::mma_sync(acc[i][j], ah[i], bh2[j], acc[i][j]);
                    wmma::mma_sync(acc[i][j], al[i], bh2[j], acc[i][j]);
                    wmma::mma_sync(acc[i][j], ah[i], bl2[j], acc[i][j]);
                }
        }
        __syncthreads();
    }

    const int b = bh >> 3, h = bh & 7;
    #pragma unroll
    for (int i = 0; i < 2; i++)
        #pragma unroll
        for (int j = 0; j < 2; j++) {
            int qq = q0 + wm * 32 + i * 16;
            int dd = h * DH + wn * 32 + j * 16;
            wmma::store_matrix_sync(
                &ctx[((size_t)(b * NQ + qq)) * DMODEL + dd],
                acc[i][j], DMODEL, wmma::mem_row_major);
        }
}

// ---------------------------------------------------------------------------
extern "C" void kernel_launch(void* const* d_in, const int* in_sizes, int n_in,
                              void* d_out, int out_size)
{
    const float* q    = (const float*)d_in[0];
    const float* kv   = (const float*)d_in[1];
    const int*   mask = (const int*)  d_in[2];
    const float* Wq   = (const float*)d_in[3];
    const float* bq   = (const float*)d_in[4];
    const float* Wk   = (const float*)d_in[5];
    const float* bk   = (const float*)d_in[6];
    const float* Wv   = (const float*)d_in[7];
    const float* bv   = (const float*)d_in[8];
    const float* Wo   = (const float*)d_in[9];
    const float* bo   = (const float*)d_in[10];
    const float* R    = (const float*)d_in[11];

    float* out = (float*)d_out;
    const size_t out_elems  = (size_t)BATCH * NQ * DMODEL;       // 4,194,304
    const size_t attn_elems = (size_t)BH * NQ * NKV;             // 67,108,864

    static float *Qp = nullptr, *Kp = nullptr, *Vp = nullptr, *ctx = nullptr, *fb = nullptr;
    if (!Qp) {
        cudaGetSymbolAddress((void**)&Qp,  g_Q);
        cudaGetSymbolAddress((void**)&Kp,  g_K);
        cudaGetSymbolAddress((void**)&Vp,  g_V);
        cudaGetSymbolAddress((void**)&ctx, g_ctx);
        cudaGetSymbolAddress((void**)&fb,  g_scores_fallback);
        cudaFuncSetAttribute(sgemm_wmma_kernel,
                             cudaFuncAttributeMaxDynamicSharedMemorySize, SG_SMEM);
        cudaFuncSetAttribute(qk_wmma_kernel,
                             cudaFuncAttributeMaxDynamicSharedMemorySize, QK_SMEM);
        cudaFuncSetAttribute(rpe_wmma_kernel,
                             cudaFuncAttributeMaxDynamicSharedMemorySize, RP_SMEM);
        cudaFuncSetAttribute(pv_wmma_kernel,
                             cudaFuncAttributeMaxDynamicSharedMemorySize, PV_SMEM);
    }

    float* scores = ((size_t)out_size >= out_elems + attn_elems) ? (out + out_elems) : fb;

    const int M = BATCH * NQ;   // 8192
    dim3 gemm_grid(DMODEL / 128, M / 64);   // (4, 128)

    // 1-3: projections (WMMA split-bf16) with [b,h,n,d] permuted store
    sgemm_wmma_kernel<<<gemm_grid, 256, SG_SMEM>>>(q,  Wq, bq, Qp, 1);
    sgemm_wmma_kernel<<<gemm_grid, 256, SG_SMEM>>>(kv, Wk, bk, Kp, 1);
    sgemm_wmma_kernel<<<gemm_grid, 256, SG_SMEM>>>(kv, Wv, bv, Vp, 1);

    // 4: S1 = Q K^T per bh (WMMA, 64x128 tiles, 2 CTAs/SM)
    dim3 qk_grid(NKV / 128, NQ / 64, BH);   // (8,16,64)
    qk_wmma_kernel<<<qk_grid, 256, QK_SMEM>>>(Qp, Kp, scores);

    // 5: S = mask ? (S1 + Q·R) * scale : -1e30  (WMMA; R read once)
    dim3 rpe_grid(NKV / 128, NQ);           // (8,1024)
    rpe_wmma_kernel<<<rpe_grid, 256, RP_SMEM>>>(Qp, R, mask, scores);

    // 6: softmax rows in place -> attn
    softmax_kernel<<<BH * NQ, 256>>>(scores);

    // 7: ctx = attn @ V (WMMA), stored [b,q,h*64+d]
    dim3 pv_grid(NQ / 128, BH);             // (8,64)
    pv_wmma_kernel<<<pv_grid, 256, PV_SMEM>>>(scores, Vp, ctx);

    // 8: out = ctx @ Wo + bo (WMMA)
    sgemm_wmma_kernel<<<gemm_grid, 256, SG_SMEM>>>(ctx, Wo, bo, out, 0);
}